// round 13
// baseline (speedup 1.0000x reference)
#include <cuda_runtime.h>
#include <cstdint>

// ---------------------------------------------------------------------------
// Problem constants
// ---------------------------------------------------------------------------
#define BATCH 8
#define NNODE 500
#define NQ    25
#define ENC   512
#define DIN   300
#define NC    70
#define NET   3
#define HOPS  3
#define MROWS (BATCH*NNODE)   // 4000
#define QROWS (BATCH*NQ)      // 200
#define MAXNZ 192

// GEMM smem geometry (u32 units) — tile 128x128, BK=32, 4-stage
#define NSTAGE  4
#define ASTRIDE 36
#define BSTRIDE 136
#define ABUF (128*ASTRIDE)          // 4608
#define BBUF (32*BSTRIDE)           // 4352
#define STAGEBUF (ABUF + BBUF)      // 8960 u32 = 35840 B
#define GEMM_SMEM (NSTAGE*STAGEBUF*4)   // 143360 bytes
#define ATTN_SMEM (NQ*ENC*4)            // 51200 bytes

// ---------------------------------------------------------------------------
// Device scratch
// ---------------------------------------------------------------------------
__device__ float g_nc  [MROWS*ENC];
__device__ float g_qc  [QROWS*ENC];
__device__ float g_L   [MROWS*ENC];
__device__ float g_L2  [MROWS*ENC];
__device__ float g_hm  [MROWS*ENC];
__device__ float g_U   [MROWS*ENC];
__device__ float g_smax[MROWS];
__device__ float g_g   [MROWS*4*ENC];
__device__ float g_h1p [4*MROWS*128];
__device__ float g_raw [MROWS];
// tf32-rounded copies of inputs
__device__ float g_Wnr [DIN*ENC];
__device__ float g_Wqr [DIN*ENC];
__device__ float g_Whr [ENC*ENC];
__device__ float g_Wcr [2*ENC*ENC];
__device__ float g_W1r [4*ENC*128];
__device__ float g_ngr [MROWS*DIN];
__device__ float g_qgr [QROWS*DIN];
// adjacency sparsity
__device__ int   g_nzc [MROWS];
__device__ int   g_nzi [MROWS*MAXNZ];
__device__ float g_nzv [MROWS*MAXNZ];

// ---------------------------------------------------------------------------
// Helpers
// ---------------------------------------------------------------------------
__device__ __forceinline__ float warpSum(float v) {
#pragma unroll
    for (int o = 16; o; o >>= 1) v += __shfl_xor_sync(0xffffffffu, v, o);
    return v;
}
__device__ __forceinline__ float warpMax(float v) {
#pragma unroll
    for (int o = 16; o; o >>= 1) v = fmaxf(v, __shfl_xor_sync(0xffffffffu, v, o));
    return v;
}
__device__ __forceinline__ float tf32r(float f) {
    uint32_t u;
    asm("cvt.rna.tf32.f32 %0, %1;" : "=r"(u) : "f"(f));
    return __uint_as_float(u);
}
__device__ __forceinline__ void mma_tf32(float* c, const uint32_t* a, const uint32_t* b) {
    asm volatile(
        "mma.sync.aligned.m16n8k8.row.col.f32.tf32.tf32.f32 "
        "{%0,%1,%2,%3}, {%4,%5,%6,%7}, {%8,%9}, {%0,%1,%2,%3};"
        : "+f"(c[0]), "+f"(c[1]), "+f"(c[2]), "+f"(c[3])
        : "r"(a[0]), "r"(a[1]), "r"(a[2]), "r"(a[3]), "r"(b[0]), "r"(b[1]));
}
__device__ __forceinline__ uint32_t smem_u32(const void* p) {
    return (uint32_t)__cvta_generic_to_shared(p);
}
__device__ __forceinline__ void cp_async16(uint32_t dst, const void* src, int sz) {
    asm volatile("cp.async.ca.shared.global [%0], [%1], 16, %2;\n"
                 :: "r"(dst), "l"(src), "r"(sz));
}
__device__ __forceinline__ void cp_commit() {
    asm volatile("cp.async.commit_group;\n" ::: "memory");
}
template<int N>
__device__ __forceinline__ void cp_wait() {
    asm volatile("cp.async.wait_group %0;\n" :: "n"(N) : "memory");
}

// Zero a 128x128 output tile (coalesced), guarded by r < M.
__device__ __forceinline__ void zero_tile(float* __restrict__ C, int ldc,
                                          int rowBlock, int colBlock, int M)
{
    const float4 z = make_float4(0.f, 0.f, 0.f, 0.f);
    for (int i = threadIdx.x; i < 128 * 32; i += 256) {
        int r = rowBlock + (i >> 5);
        int c4 = (i & 31) * 4;
        if (r < M)
            *reinterpret_cast<float4*>(C + (size_t)r * ldc + colBlock + c4) = z;
    }
}

// Is any row of [rowBlock, rowBlock+128) active (i < nlen[b])?
__device__ __forceinline__ bool tile_active(int rowBlock, const int* __restrict__ nlen)
{
    int b0 = rowBlock / NNODE;
    int b1 = (rowBlock + 127) / NNODE;
    if (b1 >= BATCH) b1 = BATCH - 1;
    bool act = false;
    for (int b = b0; b <= b1; b++) {
        int seg = rowBlock - b * NNODE;
        if (seg < 0) seg = 0;
        if (seg < nlen[b]) act = true;
    }
    return act;
}

// ---------------------------------------------------------------------------
// round_kernel: tf32-round all GEMM operand inputs (float4 granularity)
// ---------------------------------------------------------------------------
#define NB_ROUND 2555    // ceil(653944/256)
__global__ void round_kernel(
    const float4* __restrict__ Wn, const float4* __restrict__ Wq,
    const float4* __restrict__ Wh, const float4* __restrict__ Wc,
    const float4* __restrict__ W1, const float4* __restrict__ ng,
    const float4* __restrict__ qg,
    float4* __restrict__ oWn, float4* __restrict__ oWq, float4* __restrict__ oWh,
    float4* __restrict__ oWc, float4* __restrict__ oW1, float4* __restrict__ ong,
    float4* __restrict__ oqg)
{
    int idx = blockIdx.x * 256 + threadIdx.x;
    const float4* src; float4* dst; int off;
    if      (idx < 38400)  { src = Wn; dst = oWn; off = idx; }
    else if (idx < 76800)  { src = Wq; dst = oWq; off = idx - 38400; }
    else if (idx < 142336) { src = Wh; dst = oWh; off = idx - 76800; }
    else if (idx < 273408) { src = Wc; dst = oWc; off = idx - 142336; }
    else if (idx < 338944) { src = W1; dst = oW1; off = idx - 273408; }
    else if (idx < 638944) { src = ng; dst = ong; off = idx - 338944; }
    else if (idx < 653944) { src = qg; dst = oqg; off = idx - 638944; }
    else return;
    float4 v = src[off];
    v.x = tf32r(v.x); v.y = tf32r(v.y); v.z = tf32r(v.z); v.w = tf32r(v.w);
    dst[off] = v;
}

// ---------------------------------------------------------------------------
// nz_kernel: build adjacency nz lists (one warp per row)
// ---------------------------------------------------------------------------
#define NB_NZ 500
__global__ void nz_kernel(const float* __restrict__ adj, int* __restrict__ nzc,
                          int* __restrict__ nzi, float* __restrict__ nzv)
{
    int gw = blockIdx.x * 8 + (threadIdx.x >> 5);
    int lane = threadIdx.x & 31;
    if (gw >= MROWS) return;
    int b = gw / NNODE;
    int i = gw - b * NNODE;
    const float* a0 = adj + ((size_t)b * NET) * NNODE * NNODE + (size_t)i * NNODE;
    const float* a1 = a0 + NNODE * NNODE;
    const float* a2 = a1 + NNODE * NNODE;
    int cnt = 0;
    for (int jb = 0; jb < NNODE; jb += 32) {
        int j = jb + lane;
        float v = 0.f;
        if (j < NNODE) v = a0[j] + a1[j] + a2[j];
        unsigned m = __ballot_sync(0xffffffffu, v != 0.f);
        int pos = cnt + __popc(m & ((1u << lane) - 1u));
        if (v != 0.f && pos < MAXNZ) {
            nzi[gw * MAXNZ + pos] = j;
            nzv[gw * MAXNZ + pos] = v;
        }
        cnt += __popc(m);
    }
    if (lane == 0) nzc[gw] = cnt;
}

// ---------------------------------------------------------------------------
// GEMM core (BK=32, tile 128x128, 8 warps, NSTAGE-deep cp.async pipeline).
// R11 fragment scheme; single change vs R11: next-stage loads issued BEFORE
// the MMA block so they overlap compute.
// ---------------------------------------------------------------------------
struct GemmCtx {
    uint32_t* sh;
    int tid, lane, warp, wm, wn, tg, tq;
};

__device__ __forceinline__ void gemm_ctx_init(GemmCtx& cx, uint32_t* sh) {
    cx.sh = sh;
    cx.tid = threadIdx.x; cx.lane = cx.tid & 31; cx.warp = cx.tid >> 5;
    cx.wm = cx.warp >> 1; cx.wn = cx.warp & 1;
    cx.tg = cx.lane >> 2; cx.tq = cx.lane & 3;
}

__device__ __forceinline__ void gemm_core(
    GemmCtx& cx,
    const float* __restrict__ A, int lda,
    const float* __restrict__ Ab, int ldab, int ksplit,
    const float* __restrict__ W, int ldw,
    int rowBlock, int colBlock, int kBase, int M, int K,
    float acc[2][8][4])
{
    uint32_t* sh = cx.sh;
    const int tid = cx.tid, tg = cx.tg, tq = cx.tq, wm = cx.wm, wn = cx.wn;

    auto loadTiles = [&](int k0, int buf) {
        uint32_t* Ad = sh + buf * STAGEBUF;
        uint32_t* Bd = Ad + ABUF;
#pragma unroll
        for (int it = 0; it < 4; it++) {
            int idx = it * 256 + tid;
            int m = idx >> 3, cc = idx & 7;
            int gr = rowBlock + m;
            int kk = k0 + cc * 4;
            int gk = kBase + kk;
            bool ok = (gr < M && kk < K);
            int gks = ok ? gk : 0;
            const float* src = (gks < ksplit)
                ? A  + (size_t)gr * lda  + gks
                : Ab + (size_t)gr * ldab + (gks - ksplit);
            cp_async16(smem_u32(Ad + m * ASTRIDE + cc * 4), src, ok ? 16 : 0);
        }
#pragma unroll
        for (int it = 0; it < 4; it++) {
            int idx = it * 256 + tid;
            int k = idx >> 5, cc = idx & 31;
            int kk = k0 + k;
            bool ok = (kk < K);
            int gks = ok ? (kBase + kk) : 0;
            const float* src = W + (size_t)gks * ldw + colBlock + cc * 4;
            cp_async16(smem_u32(Bd + k * BSTRIDE + cc * 4), src, ok ? 16 : 0);
        }
        cp_commit();
    };

    const int nsteps = (K + 31) / 32;

#pragma unroll
    for (int i = 0; i < NSTAGE - 1; i++)
        loadTiles(i * 32, i);

    for (int s = 0; s < nsteps; s++) {
        cp_wait<NSTAGE - 2>();
        __syncthreads();

        // issue next stage's loads first; buffer (s-1)%NSTAGE last read at
        // step s-1, fenced by the syncthreads above.
        loadTiles((s + NSTAGE - 1) * 32, (s + NSTAGE - 1) % NSTAGE);

        const int buf = s % NSTAGE;
        uint32_t* As = sh + buf * STAGEBUF;
        uint32_t* Bs = As + ABUF;
#pragma unroll
        for (int ks = 0; ks < 4; ks++) {
            const int kb = ks * 8;
            uint32_t af[2][4], bf[8][2];
#pragma unroll
            for (int mt = 0; mt < 2; mt++) {
                int r0 = wm * 32 + mt * 16 + tg;
                af[mt][0] = As[(r0    ) * ASTRIDE + kb + tq];
                af[mt][1] = As[(r0 + 8) * ASTRIDE + kb + tq];
                af[mt][2] = As[(r0    ) * ASTRIDE + kb + tq + 4];
                af[mt][3] = As[(r0 + 8) * ASTRIDE + kb + tq + 4];
            }
#pragma unroll
            for (int nt = 0; nt < 8; nt++) {
                int c0 = wn * 64 + nt * 8 + tg;
                bf[nt][0] = Bs[(kb + tq    ) * BSTRIDE + c0];
                bf[nt][1] = Bs[(kb + tq + 4) * BSTRIDE + c0];
            }
#pragma unroll
            for (int mt = 0; mt < 2; mt++)
#pragma unroll
                for (int nt = 0; nt < 8; nt++)
                    mma_tf32(acc[mt][nt], af[mt], bf[nt]);
        }
    }
    cp_wait<0>();
    __syncthreads();
}

// ---------------------------------------------------------------------------
// Combined compress GEMM: blockIdx.y<32 -> nodes (tanh + masked L),
// else -> query (plain). K=300.
// ---------------------------------------------------------------------------
__global__ void __launch_bounds__(256, 1) gemm_compress(
    const float* __restrict__ ng, const float* __restrict__ Wn,
    const float* __restrict__ bn, float* __restrict__ nc,
    float* __restrict__ L, const int* __restrict__ nlen,
    const float* __restrict__ qg, const float* __restrict__ Wq,
    const float* __restrict__ bq, float* __restrict__ qc)
{
    extern __shared__ uint32_t sh_[];
    GemmCtx cx; gemm_ctx_init(cx, sh_);
    float acc[2][8][4];
#pragma unroll
    for (int i = 0; i < 2; i++)
#pragma unroll
        for (int j = 0; j < 8; j++)
#pragma unroll
            for (int l = 0; l < 4; l++) acc[i][j][l] = 0.f;

    const bool isQ = blockIdx.y >= 32;
    const float* A    = isQ ? qg : ng;
    const float* W    = isQ ? Wq : Wn;
    const float* bias = isQ ? bq : bn;
    float* C          = isQ ? qc : nc;
    const int M       = isQ ? QROWS : MROWS;
    const int rowBlock = (isQ ? blockIdx.y - 32 : blockIdx.y) * 128;
    const int colBlock = blockIdx.x * 128;

    gemm_core(cx, A, DIN, A, DIN, DIN, W, ENC,
              rowBlock, colBlock, 0, M, DIN, acc);

#pragma unroll
    for (int mt = 0; mt < 2; mt++) {
#pragma unroll
        for (int half = 0; half < 2; half++) {
            int r = rowBlock + cx.wm * 32 + mt * 16 + cx.tg + half * 8;
            if (r >= M) continue;
            float rowmask = 1.f;
            if (!isQ) {
                int bb = r / NNODE;
                int ii = r - bb * NNODE;
                rowmask = (ii < nlen[bb]) ? 1.f : 0.f;
            }
#pragma unroll
            for (int nt = 0; nt < 8; nt++) {
#pragma unroll
                for (int e = 0; e < 2; e++) {
                    int c = colBlock + cx.wn * 64 + nt * 8 + cx.tq * 2 + e;
                    float v = acc[mt][nt][half * 2 + e] + bias[c];
                    size_t off = (size_t)r * ENC + c;
                    if (isQ) {
                        C[off] = v;
                    } else {
                        float t = tanhf(v);
                        C[off] = t;
                        L[off] = tf32r(t) * rowmask;
                    }
                }
            }
        }
    }
}

// ---------------------------------------------------------------------------
// Hop GEMM A: hm = (L @ Wh + bh) * nmask.
// Dead tiles: zero-fill only on hop 0.
// ---------------------------------------------------------------------------
__global__ void __launch_bounds__(256, 1) gemm_hm(
    const float* __restrict__ Lc, const float* __restrict__ Wh,
    const float* __restrict__ bh, float* __restrict__ hm,
    const int* __restrict__ nlen, int hop)
{
    const int rowBlock = blockIdx.y * 128;
    const int colBlock = blockIdx.x * 128;
    const int M = MROWS;

    if (!tile_active(rowBlock, nlen)) {
        if (hop == 0) zero_tile(hm, ENC, rowBlock, colBlock, M);
        return;
    }

    extern __shared__ uint32_t sh_[];
    GemmCtx cx; gemm_ctx_init(cx, sh_);
    float acc[2][8][4];
#pragma unroll
    for (int i = 0; i < 2; i++)
#pragma unroll
        for (int j = 0; j < 8; j++)
#pragma unroll
            for (int l = 0; l < 4; l++) acc[i][j][l] = 0.f;

    gemm_core(cx, Lc, ENC, Lc, ENC, ENC, Wh, ENC,
              rowBlock, colBlock, 0, M, ENC, acc);

#pragma unroll
    for (int mt = 0; mt < 2; mt++) {
#pragma unroll
        for (int half = 0; half < 2; half++) {
            int r = rowBlock + cx.wm * 32 + mt * 16 + cx.tg + half * 8;
            if (r >= M) continue;
            int bb = r / NNODE;
            int ii = r - bb * NNODE;
            float rowmask = (ii < nlen[bb]) ? 1.f : 0.f;
#pragma unroll
            for (int nt = 0; nt < 8; nt++) {
#pragma unroll
                for (int e = 0; e < 2; e++) {
                    int c = colBlock + cx.wn * 64 + nt * 8 + cx.tq * 2 + e;
                    float v = acc[mt][nt][half * 2 + e] + bh[c];
                    hm[(size_t)r * ENC + c] = v * rowmask;
                }
            }
        }
    }
}

// ---------------------------------------------------------------------------
// Hop GEMM B: att = sigmoid([U,L] @ Wc + bc)*nmask;
//             Lnew = tf32r(att*tanh(U) + (1-att)*Lold)
// Dead tiles: zero-fill only on hop 0.
// ---------------------------------------------------------------------------
__global__ void __launch_bounds__(256, 1) gemm_att(
    const float* __restrict__ U, const float* __restrict__ Lold,
    const float* __restrict__ Wc, const float* __restrict__ bc,
    const int* __restrict__ nlen, float* __restrict__ Lnew, int hop)
{
    const int rowBlock = blockIdx.y * 128;
    const int colBlock = blockIdx.x * 128;
    const int M = MROWS;

    if (!tile_active(rowBlock, nlen)) {
        if (hop == 0) zero_tile(Lnew, ENC, rowBlock, colBlock, M);
        return;
    }

    extern __shared__ uint32_t sh_[];
    GemmCtx cx; gemm_ctx_init(cx, sh_);
    float acc[2][8][4];
#pragma unroll
    for (int i = 0; i < 2; i++)
#pragma unroll
        for (int j = 0; j < 8; j++)
#pragma unroll
            for (int l = 0; l < 4; l++) acc[i][j][l] = 0.f;

    gemm_core(cx, U, ENC, Lold, ENC, ENC, Wc, ENC,
              rowBlock, colBlock, 0, M, 2 * ENC, acc);

#pragma unroll
    for (int mt = 0; mt < 2; mt++) {
#pragma unroll
        for (int half = 0; half < 2; half++) {
            int r = rowBlock + cx.wm * 32 + mt * 16 + cx.tg + half * 8;
            if (r >= M) continue;
            int bb = r / NNODE;
            int ii = r - bb * NNODE;
            float rowmask = (ii < nlen[bb]) ? 1.f : 0.f;
#pragma unroll
            for (int nt = 0; nt < 8; nt++) {
#pragma unroll
                for (int e = 0; e < 2; e++) {
                    int c = colBlock + cx.wn * 64 + nt * 8 + cx.tq * 2 + e;
                    float v = acc[mt][nt][half * 2 + e] + bc[c];
                    size_t off = (size_t)r * ENC + c;
                    float att = rowmask / (1.f + __expf(-v));
                    Lnew[off] = tf32r(att * tanhf(U[off]) +
                                      (1.f - att) * Lold[off]);
                }
            }
        }
    }
}

// ---------------------------------------------------------------------------
// W1 GEMM: split-K=4; slab z
// ---------------------------------------------------------------------------
__global__ void __launch_bounds__(256, 1) gemm_w1(
    const float* __restrict__ g, const float* __restrict__ W1,
    float* __restrict__ h1p)
{
    extern __shared__ uint32_t sh_[];
    GemmCtx cx; gemm_ctx_init(cx, sh_);
    float acc[2][8][4];
#pragma unroll
    for (int i = 0; i < 2; i++)
#pragma unroll
        for (int j = 0; j < 8; j++)
#pragma unroll
            for (int l = 0; l < 4; l++) acc[i][j][l] = 0.f;

    const int rowBlock = blockIdx.y * 128;
    const int colBlock = 0;
    const int z = blockIdx.z;
    const int M = MROWS;

    gemm_core(cx, g, 4*ENC, g, 4*ENC, 4*ENC, W1, 128,
              rowBlock, colBlock, z * 512, M, 512, acc);

#pragma unroll
    for (int mt = 0; mt < 2; mt++) {
#pragma unroll
        for (int half = 0; half < 2; half++) {
            int r = rowBlock + cx.wm * 32 + mt * 16 + cx.tg + half * 8;
            if (r >= M) continue;
#pragma unroll
            for (int nt = 0; nt < 8; nt++) {
#pragma unroll
                for (int e = 0; e < 2; e++) {
                    int c = colBlock + cx.wn * 64 + nt * 8 + cx.tq * 2 + e;
                    float v = acc[mt][nt][half * 2 + e];
                    h1p[((size_t)z * M + r) * 128 + c] = v;
                }
            }
        }
    }
}

// ---------------------------------------------------------------------------
// U[m,:] = sum_t val[t]*hm[b, idx[t], :] + hm[m,:]; tf32-rounded.
// Masked rows: zeros written only at hop 0.
// ---------------------------------------------------------------------------
__global__ void spmm_nz(const int* __restrict__ nzc, const int* __restrict__ nzi,
                        const float* __restrict__ nzv, const float* __restrict__ adj,
                        const float* __restrict__ hm, float* __restrict__ U,
                        const int* __restrict__ nlen, int hop)
{
    const int m = blockIdx.x;
    const int b = m / NNODE;
    const int i = m - b * NNODE;
    const int d0 = threadIdx.x * 4;

    if (i >= nlen[b]) {
        if (hop == 0)
            *reinterpret_cast<float4*>(U + (size_t)m * ENC + d0) =
                make_float4(0.f, 0.f, 0.f, 0.f);
        return;
    }

    const float* hmb = hm + (size_t)b * NNODE * ENC;
    int cnt = nzc[m];
    float4 acc = *reinterpret_cast<const float4*>(hm + (size_t)m * ENC + d0);

    if (cnt <= MAXNZ) {
        __shared__ int   si[MAXNZ];
        __shared__ float sv[MAXNZ];
        for (int t = threadIdx.x; t < cnt; t += 128) {
            si[t] = nzi[m * MAXNZ + t];
            sv[t] = nzv[m * MAXNZ + t];
        }
        __syncthreads();
#pragma unroll 4
        for (int t = 0; t < cnt; t++) {
            float a = sv[t];
            const float4 hv = *reinterpret_cast<const float4*>(
                hmb + (size_t)si[t] * ENC + d0);
            acc.x += a * hv.x; acc.y += a * hv.y;
            acc.z += a * hv.z; acc.w += a * hv.w;
        }
    } else {
        const float* a0 = adj + ((size_t)b * NET) * NNODE * NNODE + (size_t)i * NNODE;
        const float* a1 = a0 + NNODE * NNODE;
        const float* a2 = a1 + NNODE * NNODE;
        for (int j = 0; j < NNODE; j++) {
            float a = a0[j] + a1[j] + a2[j];
            if (a != 0.f) {
                const float4 hv = *reinterpret_cast<const float4*>(
                    hmb + (size_t)j * ENC + d0);
                acc.x += a * hv.x; acc.y += a * hv.y;
                acc.z += a * hv.z; acc.w += a * hv.w;
            }
        }
    }
    acc.x = tf32r(acc.x); acc.y = tf32r(acc.y);
    acc.z = tf32r(acc.z); acc.w = tf32r(acc.w);
    *reinterpret_cast<float4*>(U + (size_t)m * ENC + d0) = acc;
}

// ---------------------------------------------------------------------------
// Attention (fused with g build, segs 0-2)
// ---------------------------------------------------------------------------
__global__ void __launch_bounds__(256) attn2(
    const float* __restrict__ L, const float* __restrict__ qc,
    const float* __restrict__ wa, const float* __restrict__ nc,
    float* __restrict__ g, float* __restrict__ smax)
{
    extern __shared__ float qs[];   // [NQ][ENC]
    __shared__ float sqv[32];
    const int b = blockIdx.y;
    const int tile = blockIdx.x;
    const int tid = threadIdx.x, lane = tid & 31, warp = tid >> 5;

    {
        const float4* src = (const float4*)(qc + (size_t)b * NQ * ENC);
        float4* dst = (float4*)qs;
        for (int i = tid; i < NQ * ENC / 4; i += 256) dst[i] = src[i];
    }
    __syncthreads();

    for (int q = warp; q < NQ; q += 8) {
        float s = 0.f;
        for (int d = lane; d < ENC; d += 32) s += qs[q * ENC + d] * wa[ENC + d];
        s = warpSum(s);
        if (lane == 0) sqv[q] = s;
    }

    float4 wan[4], was[4];
#pragma unroll
    for (int j = 0; j < 4; j++) {
        wan[j] = *(const float4*)(wa + j * 128 + lane * 4);
        was[j] = *(const float4*)(wa + 2 * ENC + j * 128 + lane * 4);
    }
    __syncthreads();

#pragma unroll
    for (int t = 0; t < 4; t++) {
        int n = tile * 32 + t * 8 + warp;
        if (n >= NNODE) continue;
        int m = b * NNODE + n;

        float4 lw[4];
        float sn = 0.f;
#pragma unroll
        for (int j = 0; j < 4; j++) {
            float4 Lv = *(const float4*)(L + (size_t)m * ENC + j * 128 + lane * 4);
            sn += Lv.x * wan[j].x + Lv.y * wan[j].y
                + Lv.z * wan[j].z + Lv.w * wan[j].w;
            lw[j].x = Lv.x * was[j].x; lw[j].y = Lv.y * was[j].y;
            lw[j].z = Lv.z * was[j].z; lw[j].w = Lv.w * was[j].w;
        }
        sn = warpSum(sn);

        float simq = -1e30f;
#pragma unroll
        for (int q = 0; q < NQ; q++) {
            float s = 0.f;
#pragma unroll
            for (int j = 0; j < 4; j++) {
                const float4 qv = *(const float4*)(qs + q * ENC + j * 128 + lane * 4);
                s += lw[j].x * qv.x + lw[j].y * qv.y
                   + lw[j].z * qv.z + lw[j].w * qv.w;
            }
            s = warpSum(s);
            if (lane == q) simq = sn + sqv[q] + s;
        }
        float mx = warpMax(lane < NQ ? simq : -1e30f);
        float e = (lane < NQ) ? __expf(simq - mx) : 0.f;
        float Z = warpSum(e);
        float p = e / Z;
        if (lane == 0) smax[m] = mx;

        float4 accv[4];
#pragma unroll
        for (int j = 0; j < 4; j++) accv[j] = make_float4(0.f, 0.f, 0.f, 0.f);
#pragma unroll
        for (int q = 0; q < NQ; q++) {
            float pq = __shfl_sync(0xffffffffu, p, q);
#pragma unroll
            for (int j = 0; j < 4; j++) {
                const float4 qv = *(const float4*)(qs + q * ENC + j * 128 + lane * 4);
                accv[j].x += pq * qv.x; accv[j].y += pq * qv.y;
                accv[j].z += pq * qv.z; accv[j].w += pq * qv.w;
            }
        }
        float* grow = g + (size_t)m * (4 * ENC);
#pragma unroll
        for (int j = 0; j < 4; j++) {
            int d = j * 128 + lane * 4;
            float4 ncv = *(const float4*)(nc + (size_t)m * ENC + d);
            float4 g0, g1, g2;
            g0.x = tf32r(ncv.x); g0.y = tf32r(ncv.y);
            g0.z = tf32r(ncv.z); g0.w = tf32r(ncv.w);
            g1.x = tf32r(accv[j].x); g1.y = tf32r(accv[j].y);
            g1.z = tf32r(accv[j].z); g1.w = tf32r(accv[j].w);
            g2.x = tf32r(ncv.x * accv[j].x); g2.y = tf32r(ncv.y * accv[j].y);
            g2.z = tf32r(ncv.z * accv[j].z); g2.w = tf32r(ncv.w * accv[j].w);
            *(float4*)(grow + d)           = g0;
            *(float4*)(grow + ENC + d)     = g1;
            *(float4*)(grow + 2 * ENC + d) = g2;
        }
    }
}

// ---------------------------------------------------------------------------
// q2n: grid (BATCH, 4). Block (b, cy) handles dims [cy*128, cy*128+128).
// Threads split (dim, n-half). Writes g segment 3 = tf32r(nc * q2n).
// ---------------------------------------------------------------------------
__global__ void q2n_kernel(const float* __restrict__ smax, const float* __restrict__ nc,
                           float* __restrict__ g)
{
    const int b = blockIdx.x;
    const int cy = blockIdx.y;
    const int tid = threadIdx.x;            // 256
    const int lane = tid & 31, warp = tid >> 5;
    __shared__ float w[NNODE];
    __shared__ float red[8];
    __shared__ float part[256];

    float mx = -1e30f;
    for (int n = tid; n < NNODE; n += 256) mx = fmaxf(mx, smax[b * NNODE + n]);
    mx = warpMax(mx);
    if (lane == 0) red[warp] = mx;
    __syncthreads();
    float bmax = red[0];
#pragma unroll
    for (int i = 1; i < 8; i++) bmax = fmaxf(bmax, red[i]);
    __syncthreads();

    float s = 0.f;
    for (int n = tid; n < NNODE; n += 256) {
        float e = __expf(smax[b * NNODE + n] - bmax);
        w[n] = e; s += e;
    }
    s = warpSum(s);
    if (lane == 0) red[warp] = s;
    __syncthreads();
    float Z = 0.f;
#pragma unroll
    for (int i = 0; i < 8; i++) Z += red[i];
    float inv = 1.f / Z;

    const int d = cy * 128 + (tid & 127);
    const int half = tid >> 7;
    const int n0 = half * 250, n1 = n0 + 250;

    float a = 0.f;
#pragma unroll 4
    for (int n = n0; n < n1; n++)
        a += (w[n] * inv) * nc[((size_t)b * NNODE + n) * ENC + d];
    part[tid] = a;
    __syncthreads();
    float q = part[tid & 127] + part[128 + (tid & 127)];

    for (int n = n0; n < n1; n++) {
        size_t m = (size_t)b * NNODE + n;
        g[m * (4 * ENC) + 3 * ENC + d] = tf32r(nc[m * ENC + d] * q);
    }
}

// ---------------------------------------------------------------------------
// raw[m] = sum_h tanh(sum_s h1p[s][m][h] + b1[h]) * W2[h] + b2
// ---------------------------------------------------------------------------
__global__ void raw2_kernel(const float* __restrict__ h1p, const float* __restrict__ b1,
                            const float* __restrict__ W2, const float* __restrict__ b2,
                            float* __restrict__ raw)
{
    int gw = (blockIdx.x * blockDim.x + threadIdx.x) >> 5;
    int lane = threadIdx.x & 31;
    if (gw >= MROWS) return;
    const size_t stride = (size_t)MROWS * 128;
    float s = 0.f;
    for (int h = lane; h < 128; h += 32) {
        size_t o = (size_t)gw * 128 + h;
        float v = h1p[o] + h1p[o + stride] + h1p[o + 2*stride] + h1p[o + 3*stride]
                + b1[h];
        s += tanhf(v) * W2[h];
    }
    s = warpSum(s);
    if (lane == 0) raw[gw] = s + b2[0];
}

// ---------------------------------------------------------------------------
// out[b,c] = max_n f(mask*raw),  f(0) = -1e6
// ---------------------------------------------------------------------------
__global__ void out_kernel(const int* __restrict__ mask, const float* __restrict__ raw,
                           float* __restrict__ out)
{
    int gw = (blockIdx.x * blockDim.x + threadIdx.x) >> 5;
    int lane = threadIdx.x & 31;
    if (gw >= BATCH * NC) return;
    int b = gw / NC, c = gw - b * NC;
    const int* mr = mask + ((size_t)b * NC + c) * NNODE;
    const float* rr = raw + b * NNODE;
    float mx = -1e30f;
    for (int n = lane; n < NNODE; n += 32) {
        float p = (float)mr[n] * rr[n];
        if (p == 0.f) p = -1e6f;
        mx = fmaxf(mx, p);
    }
    mx = warpMax(mx);
    if (lane == 0) out[gw] = mx;
}

// ---------------------------------------------------------------------------
// Launch (round_kernel ∥ nz_kernel on a side stream; fork/join via events)
// ---------------------------------------------------------------------------
extern "C" void kernel_launch(void* const* d_in, const int* in_sizes, int n_in,
                              void* d_out, int out_size)
{
    const float* nodes_glove = (const float*)d_in[0];
    const float* query_glove = (const float*)d_in[1];
    const float* adj         = (const float*)d_in[2];
    const int*   nlen        = (const int*)  d_in[3];
    const int*   mask        = (const int*)  d_in[4];
    const float* Wn = (const float*)d_in[5];
    const float* bn = (const float*)d_in[6];
    const float* Wq = (const float*)d_in[7];
    const float* bq = (const float*)d_in[8];
    const float* Wh = (const float*)d_in[9];
    const float* bh = (const float*)d_in[10];
    const float* Wc = (const float*)d_in[11];
    const float* bc = (const float*)d_in[12];
    const float* wa = (const float*)d_in[13];
    const float* W1 = (const float*)d_in[14];
    const float* b1 = (const float*)d_in[15];
    const float* W2 = (const float*)d_in[16];
    const float* b2 = (const float*)d_in[17];
    float* out = (float*)d_out;

    float *p_nc, *p_qc, *p_L, *p_L2, *p_hm, *p_U,
          *p_smax, *p_g, *p_h1p, *p_raw;
    float *p_Wnr, *p_Wqr, *p_Whr, *p_Wcr, *p_W1r, *p_ngr, *p_qgr;
    float *p_nzv; int *p_nzc, *p_nzi;
    cudaGetSymbolAddress((void**)&p_nc,  g_nc);
    cudaGetSymbolAddress((void**)&p_qc,  g_qc);
    cudaGetSymbolAddress((void**)&p_L,   g_L);
    cudaGetSymbolAddress((void**)&p_L2,  g_L2);
    cudaGetSymbolAddress((void**)&p_hm,  g_hm);
    cudaGetSymbolAddress((void**)&p_U,   g_U);
    cudaGetSymbolAddress((void**)&p_smax,g_smax);
    cudaGetSymbolAddress((void**)&p_g,   g_g);
    cudaGetSymbolAddress((void**)&p_h1p, g_h1p);
    cudaGetSymbolAddress((void**)&p_raw, g_raw);
    cudaGetSymbolAddress((void**)&p_Wnr, g_Wnr);
    cudaGetSymbolAddress((void**)&p_Wqr, g_Wqr);
    cudaGetSymbolAddress((void**)&p_Whr, g_Whr);
    cudaGetSymbolAddress((void**)&p_Wcr, g_Wcr);
    cudaGetSymbolAddress((void**)&p_W1r, g_W1r);
    cudaGetSymbolAddress((void**)&p_ngr, g_ngr);
    cudaGetSymbolAddress((void**)&p_qgr, g_qgr);
    cudaGetSymbolAddress((void**)&p_nzc, g_nzc);
    cudaGetSymbolAddress((void**)&p_nzi, g_nzi);
    cudaGetSymbolAddress((void**)&p_nzv, g_nzv);

    cudaFuncSetAttribute(gemm_compress, cudaFuncAttributeMaxDynamicSharedMemorySize, GEMM_SMEM);
    cudaFuncSetAttribute(gemm_hm,       cudaFuncAttributeMaxDynamicSharedMemorySize, GEMM_SMEM);
    cudaFuncSetAttribute(gemm_att,      cudaFuncAttributeMaxDynamicSharedMemorySize, GEMM_SMEM);
    cudaFuncSetAttribute(gemm_w1,       cudaFuncAttributeMaxDynamicSharedMemorySize, GEMM_SMEM);
    cudaFuncSetAttribute(attn2,         cudaFuncAttributeMaxDynamicSharedMemorySize, ATTN_SMEM);

    // side stream + events created once (static: no per-call alloc churn;
    // creation is not device-memory allocation)
    static cudaStream_t s2 = nullptr;
    static cudaEvent_t evFork = nullptr, evJoin = nullptr;
    if (!s2) {
        cudaStreamCreateWithFlags(&s2, cudaStreamNonBlocking);
        cudaEventCreateWithFlags(&evFork, cudaEventDisableTiming);
        cudaEventCreateWithFlags(&evJoin, cudaEventDisableTiming);
    }

    // fork: nz on side stream, round on main stream (independent)
    cudaEventRecord(evFork, 0);
    cudaStreamWaitEvent(s2, evFork, 0);
    nz_kernel<<<NB_NZ, 256, 0, s2>>>(adj, p_nzc, p_nzi, p_nzv);
    round_kernel<<<NB_ROUND, 256>>>(
        (const float4*)Wn, (const float4*)Wq, (const float4*)Wh,
        (const float4*)Wc, (const float4*)W1,
        (const float4*)nodes_glove, (const float4*)query_glove,
        (float4*)p_Wnr, (float4*)p_Wqr, (float4*)p_Whr,
        (float4*)p_Wcr, (float4*)p_W1r, (float4*)p_ngr, (float4*)p_qgr);
    cudaEventRecord(evJoin, s2);
    cudaStreamWaitEvent(0, evJoin, 0);

    gemm_compress<<<dim3(ENC/128, 34), 256, GEMM_SMEM>>>(
        p_ngr, p_Wnr, bn, p_nc, p_L, nlen, p_qgr, p_Wqr, bq, p_qc);

    float* Lc = p_L;
    float* Ln = p_L2;
    for (int h = 0; h < HOPS; h++) {
        gemm_hm<<<dim3(ENC/128, 32), 256, GEMM_SMEM>>>(Lc, p_Whr, bh, p_hm, nlen, h);
        spmm_nz<<<MROWS, 128>>>(p_nzc, p_nzi, p_nzv, adj, p_hm, p_U, nlen, h);
        gemm_att<<<dim3(ENC/128, 32), 256, GEMM_SMEM>>>(p_U, Lc, p_Wcr, bc, nlen, Ln, h);
        float* t = Lc; Lc = Ln; Ln = t;
    }

    attn2<<<dim3(16, 8), 256, ATTN_SMEM>>>(Lc, p_qc, wa, p_nc, p_g, p_smax);
    q2n_kernel<<<dim3(BATCH, 4), 256>>>(p_smax, p_nc, p_g);

    gemm_w1<<<dim3(1, 32, 4), 256, GEMM_SMEM>>>(p_g, p_W1r, p_h1p);
    raw2_kernel<<<(MROWS*32 + 255) / 256, 256>>>(p_h1p, b1, W2, b2, p_raw);

    out_kernel<<<(BATCH*NC*32 + 255) / 256, 256>>>(mask, p_raw, out);
}

// round 14
// speedup vs baseline: 1.0494x; 1.0494x over previous
#include <cuda_runtime.h>
#include <cstdint>

// ---------------------------------------------------------------------------
// Problem constants
// ---------------------------------------------------------------------------
#define BATCH 8
#define NNODE 500
#define NQ    25
#define ENC   512
#define DIN   300
#define NC    70
#define NET   3
#define HOPS  3
#define MROWS (BATCH*NNODE)   // 4000
#define QROWS (BATCH*NQ)      // 200
#define MAXNZ 192

// GEMM smem geometry (u32 units) — tile 128x128, BK=32, 4-stage
#define NSTAGE  4
#define ASTRIDE 36
#define BSTRIDE 132
#define ABUF (128*ASTRIDE)          // 4608
#define BBUF (32*BSTRIDE)           // 4224
#define STAGEBUF (ABUF + BBUF)      // 8832 u32 = 35328 B
#define GEMM_SMEM (NSTAGE*STAGEBUF*4)   // 141312 bytes
#define ATTN_SMEM (NQ*ENC*4)            // 51200 bytes

// ---------------------------------------------------------------------------
// Device scratch
// ---------------------------------------------------------------------------
__device__ float g_nc  [MROWS*ENC];
__device__ float g_qc  [QROWS*ENC];
__device__ float g_L   [MROWS*ENC];
__device__ float g_L2  [MROWS*ENC];
__device__ float g_hm  [MROWS*ENC];
__device__ float g_U   [MROWS*ENC];
__device__ float g_smax[MROWS];
__device__ float g_g   [MROWS*4*ENC];
__device__ float g_h1p [4*MROWS*128];
__device__ float g_raw [MROWS];
// tf32-rounded copies of inputs
__device__ float g_Wnr [DIN*ENC];
__device__ float g_Wqr [DIN*ENC];
__device__ float g_Whr [ENC*ENC];
__device__ float g_Wcr [2*ENC*ENC];
__device__ float g_W1r [4*ENC*128];
__device__ float g_ngr [MROWS*DIN];
__device__ float g_qgr [QROWS*DIN];
// adjacency sparsity
__device__ int   g_nzc [MROWS];
__device__ int   g_nzi [MROWS*MAXNZ];
__device__ float g_nzv [MROWS*MAXNZ];

// ---------------------------------------------------------------------------
// Helpers
// ---------------------------------------------------------------------------
__device__ __forceinline__ float warpSum(float v) {
#pragma unroll
    for (int o = 16; o; o >>= 1) v += __shfl_xor_sync(0xffffffffu, v, o);
    return v;
}
__device__ __forceinline__ float warpMax(float v) {
#pragma unroll
    for (int o = 16; o; o >>= 1) v = fmaxf(v, __shfl_xor_sync(0xffffffffu, v, o));
    return v;
}
__device__ __forceinline__ float tf32r(float f) {
    uint32_t u;
    asm("cvt.rna.tf32.f32 %0, %1;" : "=r"(u) : "f"(f));
    return __uint_as_float(u);
}
// pack two fp32 -> f16x2 (lo = first arg)
__device__ __forceinline__ uint32_t packh2(float lo, float hi) {
    uint32_t r;
    asm("cvt.rn.f16x2.f32 %0, %1, %2;" : "=r"(r) : "f"(hi), "f"(lo));
    return r;
}
// m16n8k16 fp16 MMA, fp32 accumulate (same acc layout as m16n8k8)
__device__ __forceinline__ void mma_f16(float* c, const uint32_t* a, const uint32_t* b) {
    asm volatile(
        "mma.sync.aligned.m16n8k16.row.col.f32.f16.f16.f32 "
        "{%0,%1,%2,%3}, {%4,%5,%6,%7}, {%8,%9}, {%0,%1,%2,%3};"
        : "+f"(c[0]), "+f"(c[1]), "+f"(c[2]), "+f"(c[3])
        : "r"(a[0]), "r"(a[1]), "r"(a[2]), "r"(a[3]), "r"(b[0]), "r"(b[1]));
}
__device__ __forceinline__ uint32_t smem_u32(const void* p) {
    return (uint32_t)__cvta_generic_to_shared(p);
}
__device__ __forceinline__ void cp_async16(uint32_t dst, const void* src, int sz) {
    asm volatile("cp.async.ca.shared.global [%0], [%1], 16, %2;\n"
                 :: "r"(dst), "l"(src), "r"(sz));
}
__device__ __forceinline__ void cp_commit() {
    asm volatile("cp.async.commit_group;\n" ::: "memory");
}
template<int N>
__device__ __forceinline__ void cp_wait() {
    asm volatile("cp.async.wait_group %0;\n" :: "n"(N) : "memory");
}

// Zero a 128x128 output tile (coalesced), guarded by r < M.
__device__ __forceinline__ void zero_tile(float* __restrict__ C, int ldc,
                                          int rowBlock, int colBlock, int M)
{
    const float4 z = make_float4(0.f, 0.f, 0.f, 0.f);
    for (int i = threadIdx.x; i < 128 * 32; i += 256) {
        int r = rowBlock + (i >> 5);
        int c4 = (i & 31) * 4;
        if (r < M)
            *reinterpret_cast<float4*>(C + (size_t)r * ldc + colBlock + c4) = z;
    }
}

// Is any row of [rowBlock, rowBlock+128) active (i < nlen[b])?
__device__ __forceinline__ bool tile_active(int rowBlock, const int* __restrict__ nlen)
{
    int b0 = rowBlock / NNODE;
    int b1 = (rowBlock + 127) / NNODE;
    if (b1 >= BATCH) b1 = BATCH - 1;
    bool act = false;
    for (int b = b0; b <= b1; b++) {
        int seg = rowBlock - b * NNODE;
        if (seg < 0) seg = 0;
        if (seg < nlen[b]) act = true;
    }
    return act;
}

// ---------------------------------------------------------------------------
// round_kernel: tf32-round all GEMM operand inputs (float4 granularity)
// ---------------------------------------------------------------------------
#define NB_ROUND 2555    // ceil(653944/256)
__global__ void round_kernel(
    const float4* __restrict__ Wn, const float4* __restrict__ Wq,
    const float4* __restrict__ Wh, const float4* __restrict__ Wc,
    const float4* __restrict__ W1, const float4* __restrict__ ng,
    const float4* __restrict__ qg,
    float4* __restrict__ oWn, float4* __restrict__ oWq, float4* __restrict__ oWh,
    float4* __restrict__ oWc, float4* __restrict__ oW1, float4* __restrict__ ong,
    float4* __restrict__ oqg)
{
    int idx = blockIdx.x * 256 + threadIdx.x;
    const float4* src; float4* dst; int off;
    if      (idx < 38400)  { src = Wn; dst = oWn; off = idx; }
    else if (idx < 76800)  { src = Wq; dst = oWq; off = idx - 38400; }
    else if (idx < 142336) { src = Wh; dst = oWh; off = idx - 76800; }
    else if (idx < 273408) { src = Wc; dst = oWc; off = idx - 142336; }
    else if (idx < 338944) { src = W1; dst = oW1; off = idx - 273408; }
    else if (idx < 638944) { src = ng; dst = ong; off = idx - 338944; }
    else if (idx < 653944) { src = qg; dst = oqg; off = idx - 638944; }
    else return;
    float4 v = src[off];
    v.x = tf32r(v.x); v.y = tf32r(v.y); v.z = tf32r(v.z); v.w = tf32r(v.w);
    dst[off] = v;
}

// ---------------------------------------------------------------------------
// nz_kernel: build adjacency nz lists (one warp per row)
// ---------------------------------------------------------------------------
#define NB_NZ 500
__global__ void nz_kernel(const float* __restrict__ adj, int* __restrict__ nzc,
                          int* __restrict__ nzi, float* __restrict__ nzv)
{
    int gw = blockIdx.x * 8 + (threadIdx.x >> 5);
    int lane = threadIdx.x & 31;
    if (gw >= MROWS) return;
    int b = gw / NNODE;
    int i = gw - b * NNODE;
    const float* a0 = adj + ((size_t)b * NET) * NNODE * NNODE + (size_t)i * NNODE;
    const float* a1 = a0 + NNODE * NNODE;
    const float* a2 = a1 + NNODE * NNODE;
    int cnt = 0;
    for (int jb = 0; jb < NNODE; jb += 32) {
        int j = jb + lane;
        float v = 0.f;
        if (j < NNODE) v = a0[j] + a1[j] + a2[j];
        unsigned m = __ballot_sync(0xffffffffu, v != 0.f);
        int pos = cnt + __popc(m & ((1u << lane) - 1u));
        if (v != 0.f && pos < MAXNZ) {
            nzi[gw * MAXNZ + pos] = j;
            nzv[gw * MAXNZ + pos] = v;
        }
        cnt += __popc(m);
    }
    if (lane == 0) nzc[gw] = cnt;
}

// ---------------------------------------------------------------------------
// GEMM core (BK=32, tile 128x128, 8 warps, NSTAGE-deep cp.async pipeline).
// smem holds fp32; fragments are packed to f16x2 in registers and fed to
// m16n8k16 fp16 MMA with fp32 accumulate (acc layout == m16n8k8 -> epilogues
// unchanged). Load/sync schedule identical to the R11 measured optimum.
// ---------------------------------------------------------------------------
struct GemmCtx {
    uint32_t* sh;
    int tid, lane, warp, wm, wn, tg, tq;
};

__device__ __forceinline__ void gemm_ctx_init(GemmCtx& cx, uint32_t* sh) {
    cx.sh = sh;
    cx.tid = threadIdx.x; cx.lane = cx.tid & 31; cx.warp = cx.tid >> 5;
    cx.wm = cx.warp >> 1; cx.wn = cx.warp & 1;
    cx.tg = cx.lane >> 2; cx.tq = cx.lane & 3;
}

__device__ __forceinline__ void gemm_core(
    GemmCtx& cx,
    const float* __restrict__ A, int lda,
    const float* __restrict__ Ab, int ldab, int ksplit,
    const float* __restrict__ W, int ldw,
    int rowBlock, int colBlock, int kBase, int M, int K,
    float acc[2][8][4])
{
    uint32_t* sh = cx.sh;
    const int tid = cx.tid, tg = cx.tg, tq = cx.tq, wm = cx.wm, wn = cx.wn;

    auto loadTiles = [&](int k0, int buf) {
        uint32_t* Ad = sh + buf * STAGEBUF;
        uint32_t* Bd = Ad + ABUF;
#pragma unroll
        for (int it = 0; it < 4; it++) {
            int idx = it * 256 + tid;
            int m = idx >> 3, cc = idx & 7;
            int gr = rowBlock + m;
            int kk = k0 + cc * 4;
            int gk = kBase + kk;
            bool ok = (gr < M && kk < K);
            int gks = ok ? gk : 0;
            const float* src = (gks < ksplit)
                ? A  + (size_t)gr * lda  + gks
                : Ab + (size_t)gr * ldab + (gks - ksplit);
            cp_async16(smem_u32(Ad + m * ASTRIDE + cc * 4), src, ok ? 16 : 0);
        }
#pragma unroll
        for (int it = 0; it < 4; it++) {
            int idx = it * 256 + tid;
            int k = idx >> 5, cc = idx & 31;
            int kk = k0 + k;
            bool ok = (kk < K);
            int gks = ok ? (kBase + kk) : 0;
            const float* src = W + (size_t)gks * ldw + colBlock + cc * 4;
            cp_async16(smem_u32(Bd + k * BSTRIDE + cc * 4), src, ok ? 16 : 0);
        }
        cp_commit();
    };

    const int nsteps = (K + 31) / 32;

#pragma unroll
    for (int i = 0; i < NSTAGE - 1; i++)
        loadTiles(i * 32, i);

    for (int s = 0; s < nsteps; s++) {
        cp_wait<NSTAGE - 2>();
        __syncthreads();

        const int buf = s % NSTAGE;
        const float* Asf = (const float*)(sh + buf * STAGEBUF);
        const float* Bsf = Asf + ABUF;

        // two k16 slices per BK=32 step
#pragma unroll
        for (int ks = 0; ks < 2; ks++) {
            const int kb = ks * 16;
            const int kr = kb + 2 * tq;
            uint32_t af[2][4], bf[8][2];
#pragma unroll
            for (int mt = 0; mt < 2; mt++) {
                int r0 = wm * 32 + mt * 16 + tg;
                float2 v0 = *(const float2*)(Asf + (size_t)r0 * ASTRIDE + kr);
                float2 v1 = *(const float2*)(Asf + (size_t)(r0 + 8) * ASTRIDE + kr);
                float2 v2 = *(const float2*)(Asf + (size_t)r0 * ASTRIDE + kr + 8);
                float2 v3 = *(const float2*)(Asf + (size_t)(r0 + 8) * ASTRIDE + kr + 8);
                af[mt][0] = packh2(v0.x, v0.y);
                af[mt][1] = packh2(v1.x, v1.y);
                af[mt][2] = packh2(v2.x, v2.y);
                af[mt][3] = packh2(v3.x, v3.y);
            }
#pragma unroll
            for (int nt = 0; nt < 8; nt++) {
                int c0 = wn * 64 + nt * 8 + tg;
                bf[nt][0] = packh2(Bsf[(size_t)(kr    ) * BSTRIDE + c0],
                                   Bsf[(size_t)(kr + 1) * BSTRIDE + c0]);
                bf[nt][1] = packh2(Bsf[(size_t)(kr + 8) * BSTRIDE + c0],
                                   Bsf[(size_t)(kr + 9) * BSTRIDE + c0]);
            }
#pragma unroll
            for (int mt = 0; mt < 2; mt++)
#pragma unroll
                for (int nt = 0; nt < 8; nt++)
                    mma_f16(acc[mt][nt], af[mt], bf[nt]);
        }

        loadTiles((s + NSTAGE - 1) * 32, (s + NSTAGE - 1) % NSTAGE);
    }
    cp_wait<0>();
    __syncthreads();
}

// ---------------------------------------------------------------------------
// Combined compress GEMM: blockIdx.y<32 -> nodes (tanh + masked L),
// else -> query (plain). K=300.
// ---------------------------------------------------------------------------
__global__ void __launch_bounds__(256, 1) gemm_compress(
    const float* __restrict__ ng, const float* __restrict__ Wn,
    const float* __restrict__ bn, float* __restrict__ nc,
    float* __restrict__ L, const int* __restrict__ nlen,
    const float* __restrict__ qg, const float* __restrict__ Wq,
    const float* __restrict__ bq, float* __restrict__ qc)
{
    extern __shared__ uint32_t sh_[];
    GemmCtx cx; gemm_ctx_init(cx, sh_);
    float acc[2][8][4];
#pragma unroll
    for (int i = 0; i < 2; i++)
#pragma unroll
        for (int j = 0; j < 8; j++)
#pragma unroll
            for (int l = 0; l < 4; l++) acc[i][j][l] = 0.f;

    const bool isQ = blockIdx.y >= 32;
    const float* A    = isQ ? qg : ng;
    const float* W    = isQ ? Wq : Wn;
    const float* bias = isQ ? bq : bn;
    float* C          = isQ ? qc : nc;
    const int M       = isQ ? QROWS : MROWS;
    const int rowBlock = (isQ ? blockIdx.y - 32 : blockIdx.y) * 128;
    const int colBlock = blockIdx.x * 128;

    gemm_core(cx, A, DIN, A, DIN, DIN, W, ENC,
              rowBlock, colBlock, 0, M, DIN, acc);

#pragma unroll
    for (int mt = 0; mt < 2; mt++) {
#pragma unroll
        for (int half = 0; half < 2; half++) {
            int r = rowBlock + cx.wm * 32 + mt * 16 + cx.tg + half * 8;
            if (r >= M) continue;
            float rowmask = 1.f;
            if (!isQ) {
                int bb = r / NNODE;
                int ii = r - bb * NNODE;
                rowmask = (ii < nlen[bb]) ? 1.f : 0.f;
            }
#pragma unroll
            for (int nt = 0; nt < 8; nt++) {
#pragma unroll
                for (int e = 0; e < 2; e++) {
                    int c = colBlock + cx.wn * 64 + nt * 8 + cx.tq * 2 + e;
                    float v = acc[mt][nt][half * 2 + e] + bias[c];
                    size_t off = (size_t)r * ENC + c;
                    if (isQ) {
                        C[off] = v;
                    } else {
                        float t = tanhf(v);
                        C[off] = t;
                        L[off] = tf32r(t) * rowmask;
                    }
                }
            }
        }
    }
}

// ---------------------------------------------------------------------------
// Hop GEMM A: hm = (L @ Wh + bh) * nmask.
// Dead tiles: zero-fill only on hop 0.
// ---------------------------------------------------------------------------
__global__ void __launch_bounds__(256, 1) gemm_hm(
    const float* __restrict__ Lc, const float* __restrict__ Wh,
    const float* __restrict__ bh, float* __restrict__ hm,
    const int* __restrict__ nlen, int hop)
{
    const int rowBlock = blockIdx.y * 128;
    const int colBlock = blockIdx.x * 128;
    const int M = MROWS;

    if (!tile_active(rowBlock, nlen)) {
        if (hop == 0) zero_tile(hm, ENC, rowBlock, colBlock, M);
        return;
    }

    extern __shared__ uint32_t sh_[];
    GemmCtx cx; gemm_ctx_init(cx, sh_);
    float acc[2][8][4];
#pragma unroll
    for (int i = 0; i < 2; i++)
#pragma unroll
        for (int j = 0; j < 8; j++)
#pragma unroll
            for (int l = 0; l < 4; l++) acc[i][j][l] = 0.f;

    gemm_core(cx, Lc, ENC, Lc, ENC, ENC, Wh, ENC,
              rowBlock, colBlock, 0, M, ENC, acc);

#pragma unroll
    for (int mt = 0; mt < 2; mt++) {
#pragma unroll
        for (int half = 0; half < 2; half++) {
            int r = rowBlock + cx.wm * 32 + mt * 16 + cx.tg + half * 8;
            if (r >= M) continue;
            int bb = r / NNODE;
            int ii = r - bb * NNODE;
            float rowmask = (ii < nlen[bb]) ? 1.f : 0.f;
#pragma unroll
            for (int nt = 0; nt < 8; nt++) {
#pragma unroll
                for (int e = 0; e < 2; e++) {
                    int c = colBlock + cx.wn * 64 + nt * 8 + cx.tq * 2 + e;
                    float v = acc[mt][nt][half * 2 + e] + bh[c];
                    hm[(size_t)r * ENC + c] = v * rowmask;
                }
            }
        }
    }
}

// ---------------------------------------------------------------------------
// Hop GEMM B: att = sigmoid([U,L] @ Wc + bc)*nmask;
//             Lnew = tf32r(att*tanh(U) + (1-att)*Lold)
// Dead tiles: zero-fill only on hop 0.
// ---------------------------------------------------------------------------
__global__ void __launch_bounds__(256, 1) gemm_att(
    const float* __restrict__ U, const float* __restrict__ Lold,
    const float* __restrict__ Wc, const float* __restrict__ bc,
    const int* __restrict__ nlen, float* __restrict__ Lnew, int hop)
{
    const int rowBlock = blockIdx.y * 128;
    const int colBlock = blockIdx.x * 128;
    const int M = MROWS;

    if (!tile_active(rowBlock, nlen)) {
        if (hop == 0) zero_tile(Lnew, ENC, rowBlock, colBlock, M);
        return;
    }

    extern __shared__ uint32_t sh_[];
    GemmCtx cx; gemm_ctx_init(cx, sh_);
    float acc[2][8][4];
#pragma unroll
    for (int i = 0; i < 2; i++)
#pragma unroll
        for (int j = 0; j < 8; j++)
#pragma unroll
            for (int l = 0; l < 4; l++) acc[i][j][l] = 0.f;

    gemm_core(cx, U, ENC, Lold, ENC, ENC, Wc, ENC,
              rowBlock, colBlock, 0, M, 2 * ENC, acc);

#pragma unroll
    for (int mt = 0; mt < 2; mt++) {
#pragma unroll
        for (int half = 0; half < 2; half++) {
            int r = rowBlock + cx.wm * 32 + mt * 16 + cx.tg + half * 8;
            if (r >= M) continue;
            int bb = r / NNODE;
            int ii = r - bb * NNODE;
            float rowmask = (ii < nlen[bb]) ? 1.f : 0.f;
#pragma unroll
            for (int nt = 0; nt < 8; nt++) {
#pragma unroll
                for (int e = 0; e < 2; e++) {
                    int c = colBlock + cx.wn * 64 + nt * 8 + cx.tq * 2 + e;
                    float v = acc[mt][nt][half * 2 + e] + bc[c];
                    size_t off = (size_t)r * ENC + c;
                    float att = rowmask / (1.f + __expf(-v));
                    Lnew[off] = tf32r(att * tanhf(U[off]) +
                                      (1.f - att) * Lold[off]);
                }
            }
        }
    }
}

// ---------------------------------------------------------------------------
// W1 GEMM: split-K=4; slab z
// ---------------------------------------------------------------------------
__global__ void __launch_bounds__(256, 1) gemm_w1(
    const float* __restrict__ g, const float* __restrict__ W1,
    float* __restrict__ h1p)
{
    extern __shared__ uint32_t sh_[];
    GemmCtx cx; gemm_ctx_init(cx, sh_);
    float acc[2][8][4];
#pragma unroll
    for (int i = 0; i < 2; i++)
#pragma unroll
        for (int j = 0; j < 8; j++)
#pragma unroll
            for (int l = 0; l < 4; l++) acc[i][j][l] = 0.f;

    const int rowBlock = blockIdx.y * 128;
    const int colBlock = 0;
    const int z = blockIdx.z;
    const int M = MROWS;

    gemm_core(cx, g, 4*ENC, g, 4*ENC, 4*ENC, W1, 128,
              rowBlock, colBlock, z * 512, M, 512, acc);

#pragma unroll
    for (int mt = 0; mt < 2; mt++) {
#pragma unroll
        for (int half = 0; half < 2; half++) {
            int r = rowBlock + cx.wm * 32 + mt * 16 + cx.tg + half * 8;
            if (r >= M) continue;
#pragma unroll
            for (int nt = 0; nt < 8; nt++) {
#pragma unroll
                for (int e = 0; e < 2; e++) {
                    int c = colBlock + cx.wn * 64 + nt * 8 + cx.tq * 2 + e;
                    float v = acc[mt][nt][half * 2 + e];
                    h1p[((size_t)z * M + r) * 128 + c] = v;
                }
            }
        }
    }
}

// ---------------------------------------------------------------------------
// U[m,:] = sum_t val[t]*hm[b, idx[t], :] + hm[m,:]; tf32-rounded.
// Masked rows: zeros written only at hop 0.
// ---------------------------------------------------------------------------
__global__ void spmm_nz(const int* __restrict__ nzc, const int* __restrict__ nzi,
                        const float* __restrict__ nzv, const float* __restrict__ adj,
                        const float* __restrict__ hm, float* __restrict__ U,
                        const int* __restrict__ nlen, int hop)
{
    const int m = blockIdx.x;
    const int b = m / NNODE;
    const int i = m - b * NNODE;
    const int d0 = threadIdx.x * 4;

    if (i >= nlen[b]) {
        if (hop == 0)
            *reinterpret_cast<float4*>(U + (size_t)m * ENC + d0) =
                make_float4(0.f, 0.f, 0.f, 0.f);
        return;
    }

    const float* hmb = hm + (size_t)b * NNODE * ENC;
    int cnt = nzc[m];
    float4 acc = *reinterpret_cast<const float4*>(hm + (size_t)m * ENC + d0);

    if (cnt <= MAXNZ) {
        __shared__ int   si[MAXNZ];
        __shared__ float sv[MAXNZ];
        for (int t = threadIdx.x; t < cnt; t += 128) {
            si[t] = nzi[m * MAXNZ + t];
            sv[t] = nzv[m * MAXNZ + t];
        }
        __syncthreads();
#pragma unroll 4
        for (int t = 0; t < cnt; t++) {
            float a = sv[t];
            const float4 hv = *reinterpret_cast<const float4*>(
                hmb + (size_t)si[t] * ENC + d0);
            acc.x += a * hv.x; acc.y += a * hv.y;
            acc.z += a * hv.z; acc.w += a * hv.w;
        }
    } else {
        const float* a0 = adj + ((size_t)b * NET) * NNODE * NNODE + (size_t)i * NNODE;
        const float* a1 = a0 + NNODE * NNODE;
        const float* a2 = a1 + NNODE * NNODE;
        for (int j = 0; j < NNODE; j++) {
            float a = a0[j] + a1[j] + a2[j];
            if (a != 0.f) {
                const float4 hv = *reinterpret_cast<const float4*>(
                    hmb + (size_t)j * ENC + d0);
                acc.x += a * hv.x; acc.y += a * hv.y;
                acc.z += a * hv.z; acc.w += a * hv.w;
            }
        }
    }
    acc.x = tf32r(acc.x); acc.y = tf32r(acc.y);
    acc.z = tf32r(acc.z); acc.w = tf32r(acc.w);
    *reinterpret_cast<float4*>(U + (size_t)m * ENC + d0) = acc;
}

// ---------------------------------------------------------------------------
// Attention (fused with g build, segs 0-2)
// ---------------------------------------------------------------------------
__global__ void __launch_bounds__(256) attn2(
    const float* __restrict__ L, const float* __restrict__ qc,
    const float* __restrict__ wa, const float* __restrict__ nc,
    float* __restrict__ g, float* __restrict__ smax)
{
    extern __shared__ float qs[];   // [NQ][ENC]
    __shared__ float sqv[32];
    const int b = blockIdx.y;
    const int tile = blockIdx.x;
    const int tid = threadIdx.x, lane = tid & 31, warp = tid >> 5;

    {
        const float4* src = (const float4*)(qc + (size_t)b * NQ * ENC);
        float4* dst = (float4*)qs;
        for (int i = tid; i < NQ * ENC / 4; i += 256) dst[i] = src[i];
    }
    __syncthreads();

    for (int q = warp; q < NQ; q += 8) {
        float s = 0.f;
        for (int d = lane; d < ENC; d += 32) s += qs[q * ENC + d] * wa[ENC + d];
        s = warpSum(s);
        if (lane == 0) sqv[q] = s;
    }

    float4 wan[4], was[4];
#pragma unroll
    for (int j = 0; j < 4; j++) {
        wan[j] = *(const float4*)(wa + j * 128 + lane * 4);
        was[j] = *(const float4*)(wa + 2 * ENC + j * 128 + lane * 4);
    }
    __syncthreads();

#pragma unroll
    for (int t = 0; t < 4; t++) {
        int n = tile * 32 + t * 8 + warp;
        if (n >= NNODE) continue;
        int m = b * NNODE + n;

        float4 lw[4];
        float sn = 0.f;
#pragma unroll
        for (int j = 0; j < 4; j++) {
            float4 Lv = *(const float4*)(L + (size_t)m * ENC + j * 128 + lane * 4);
            sn += Lv.x * wan[j].x + Lv.y * wan[j].y
                + Lv.z * wan[j].z + Lv.w * wan[j].w;
            lw[j].x = Lv.x * was[j].x; lw[j].y = Lv.y * was[j].y;
            lw[j].z = Lv.z * was[j].z; lw[j].w = Lv.w * was[j].w;
        }
        sn = warpSum(sn);

        float simq = -1e30f;
#pragma unroll
        for (int q = 0; q < NQ; q++) {
            float s = 0.f;
#pragma unroll
            for (int j = 0; j < 4; j++) {
                const float4 qv = *(const float4*)(qs + q * ENC + j * 128 + lane * 4);
                s += lw[j].x * qv.x + lw[j].y * qv.y
                   + lw[j].z * qv.z + lw[j].w * qv.w;
            }
            s = warpSum(s);
            if (lane == q) simq = sn + sqv[q] + s;
        }
        float mx = warpMax(lane < NQ ? simq : -1e30f);
        float e = (lane < NQ) ? __expf(simq - mx) : 0.f;
        float Z = warpSum(e);
        float p = e / Z;
        if (lane == 0) smax[m] = mx;

        float4 accv[4];
#pragma unroll
        for (int j = 0; j < 4; j++) accv[j] = make_float4(0.f, 0.f, 0.f, 0.f);
#pragma unroll
        for (int q = 0; q < NQ; q++) {
            float pq = __shfl_sync(0xffffffffu, p, q);
#pragma unroll
            for (int j = 0; j < 4; j++) {
                const float4 qv = *(const float4*)(qs + q * ENC + j * 128 + lane * 4);
                accv[j].x += pq * qv.x; accv[j].y += pq * qv.y;
                accv[j].z += pq * qv.z; accv[j].w += pq * qv.w;
            }
        }
        float* grow = g + (size_t)m * (4 * ENC);
#pragma unroll
        for (int j = 0; j < 4; j++) {
            int d = j * 128 + lane * 4;
            float4 ncv = *(const float4*)(nc + (size_t)m * ENC + d);
            float4 g0, g1, g2;
            g0.x = tf32r(ncv.x); g0.y = tf32r(ncv.y);
            g0.z = tf32r(ncv.z); g0.w = tf32r(ncv.w);
            g1.x = tf32r(accv[j].x); g1.y = tf32r(accv[j].y);
            g1.z = tf32r(accv[j].z); g1.w = tf32r(accv[j].w);
            g2.x = tf32r(ncv.x * accv[j].x); g2.y = tf32r(ncv.y * accv[j].y);
            g2.z = tf32r(ncv.z * accv[j].z); g2.w = tf32r(ncv.w * accv[j].w);
            *(float4*)(grow + d)           = g0;
            *(float4*)(grow + ENC + d)     = g1;
            *(float4*)(grow + 2 * ENC + d) = g2;
        }
    }
}

// ---------------------------------------------------------------------------
// q2n: grid (BATCH, 4). Block (b, cy) handles dims [cy*128, cy*128+128).
// Threads split (dim, n-half). Writes g segment 3 = tf32r(nc * q2n).
// ---------------------------------------------------------------------------
__global__ void q2n_kernel(const float* __restrict__ smax, const float* __restrict__ nc,
                           float* __restrict__ g)
{
    const int b = blockIdx.x;
    const int cy = blockIdx.y;
    const int tid = threadIdx.x;            // 256
    const int lane = tid & 31, warp = tid >> 5;
    __shared__ float w[NNODE];
    __shared__ float red[8];
    __shared__ float part[256];

    float mx = -1e30f;
    for (int n = tid; n < NNODE; n += 256) mx = fmaxf(mx, smax[b * NNODE + n]);
    mx = warpMax(mx);
    if (lane == 0) red[warp] = mx;
    __syncthreads();
    float bmax = red[0];
#pragma unroll
    for (int i = 1; i < 8; i++) bmax = fmaxf(bmax, red[i]);
    __syncthreads();

    float s = 0.f;
    for (int n = tid; n < NNODE; n += 256) {
        float e = __expf(smax[b * NNODE + n] - bmax);
        w[n] = e; s += e;
    }
    s = warpSum(s);
    if (lane == 0) red[warp] = s;
    __syncthreads();
    float Z = 0.f;
#pragma unroll
    for (int i = 0; i < 8; i++) Z += red[i];
    float inv = 1.f / Z;

    const int d = cy * 128 + (tid & 127);
    const int half = tid >> 7;
    const int n0 = half * 250, n1 = n0 + 250;

    float a = 0.f;
#pragma unroll 4
    for (int n = n0; n < n1; n++)
        a += (w[n] * inv) * nc[((size_t)b * NNODE + n) * ENC + d];
    part[tid] = a;
    __syncthreads();
    float q = part[tid & 127] + part[128 + (tid & 127)];

    for (int n = n0; n < n1; n++) {
        size_t m = (size_t)b * NNODE + n;
        g[m * (4 * ENC) + 3 * ENC + d] = tf32r(nc[m * ENC + d] * q);
    }
}

// ---------------------------------------------------------------------------
// raw[m] = sum_h tanh(sum_s h1p[s][m][h] + b1[h]) * W2[h] + b2
// ---------------------------------------------------------------------------
__global__ void raw2_kernel(const float* __restrict__ h1p, const float* __restrict__ b1,
                            const float* __restrict__ W2, const float* __restrict__ b2,
                            float* __restrict__ raw)
{
    int gw = (blockIdx.x * blockDim.x + threadIdx.x) >> 5;
    int lane = threadIdx.x & 31;
    if (gw >= MROWS) return;
    const size_t stride = (size_t)MROWS * 128;
    float s = 0.f;
    for (int h = lane; h < 128; h += 32) {
        size_t o = (size_t)gw * 128 + h;
        float v = h1p[o] + h1p[o + stride] + h1p[o + 2*stride] + h1p[o + 3*stride]
                + b1[h];
        s += tanhf(v) * W2[h];
    }
    s = warpSum(s);
    if (lane == 0) raw[gw] = s + b2[0];
}

// ---------------------------------------------------------------------------
// out[b,c] = max_n f(mask*raw),  f(0) = -1e6
// ---------------------------------------------------------------------------
__global__ void out_kernel(const int* __restrict__ mask, const float* __restrict__ raw,
                           float* __restrict__ out)
{
    int gw = (blockIdx.x * blockDim.x + threadIdx.x) >> 5;
    int lane = threadIdx.x & 31;
    if (gw >= BATCH * NC) return;
    int b = gw / NC, c = gw - b * NC;
    const int* mr = mask + ((size_t)b * NC + c) * NNODE;
    const float* rr = raw + b * NNODE;
    float mx = -1e30f;
    for (int n = lane; n < NNODE; n += 32) {
        float p = (float)mr[n] * rr[n];
        if (p == 0.f) p = -1e6f;
        mx = fmaxf(mx, p);
    }
    mx = warpMax(mx);
    if (lane == 0) out[gw] = mx;
}

// ---------------------------------------------------------------------------
// Launch (R11 structure)
// ---------------------------------------------------------------------------
extern "C" void kernel_launch(void* const* d_in, const int* in_sizes, int n_in,
                              void* d_out, int out_size)
{
    const float* nodes_glove = (const float*)d_in[0];
    const float* query_glove = (const float*)d_in[1];
    const float* adj         = (const float*)d_in[2];
    const int*   nlen        = (const int*)  d_in[3];
    const int*   mask        = (const int*)  d_in[4];
    const float* Wn = (const float*)d_in[5];
    const float* bn = (const float*)d_in[6];
    const float* Wq = (const float*)d_in[7];
    const float* bq = (const float*)d_in[8];
    const float* Wh = (const float*)d_in[9];
    const float* bh = (const float*)d_in[10];
    const float* Wc = (const float*)d_in[11];
    const float* bc = (const float*)d_in[12];
    const float* wa = (const float*)d_in[13];
    const float* W1 = (const float*)d_in[14];
    const float* b1 = (const float*)d_in[15];
    const float* W2 = (const float*)d_in[16];
    const float* b2 = (const float*)d_in[17];
    float* out = (float*)d_out;

    float *p_nc, *p_qc, *p_L, *p_L2, *p_hm, *p_U,
          *p_smax, *p_g, *p_h1p, *p_raw;
    float *p_Wnr, *p_Wqr, *p_Whr, *p_Wcr, *p_W1r, *p_ngr, *p_qgr;
    float *p_nzv; int *p_nzc, *p_nzi;
    cudaGetSymbolAddress((void**)&p_nc,  g_nc);
    cudaGetSymbolAddress((void**)&p_qc,  g_qc);
    cudaGetSymbolAddress((void**)&p_L,   g_L);
    cudaGetSymbolAddress((void**)&p_L2,  g_L2);
    cudaGetSymbolAddress((void**)&p_hm,  g_hm);
    cudaGetSymbolAddress((void**)&p_U,   g_U);
    cudaGetSymbolAddress((void**)&p_smax,g_smax);
    cudaGetSymbolAddress((void**)&p_g,   g_g);
    cudaGetSymbolAddress((void**)&p_h1p, g_h1p);
    cudaGetSymbolAddress((void**)&p_raw, g_raw);
    cudaGetSymbolAddress((void**)&p_Wnr, g_Wnr);
    cudaGetSymbolAddress((void**)&p_Wqr, g_Wqr);
    cudaGetSymbolAddress((void**)&p_Whr, g_Whr);
    cudaGetSymbolAddress((void**)&p_Wcr, g_Wcr);
    cudaGetSymbolAddress((void**)&p_W1r, g_W1r);
    cudaGetSymbolAddress((void**)&p_ngr, g_ngr);
    cudaGetSymbolAddress((void**)&p_qgr, g_qgr);
    cudaGetSymbolAddress((void**)&p_nzc, g_nzc);
    cudaGetSymbolAddress((void**)&p_nzi, g_nzi);
    cudaGetSymbolAddress((void**)&p_nzv, g_nzv);

    cudaFuncSetAttribute(gemm_compress, cudaFuncAttributeMaxDynamicSharedMemorySize, GEMM_SMEM);
    cudaFuncSetAttribute(gemm_hm,       cudaFuncAttributeMaxDynamicSharedMemorySize, GEMM_SMEM);
    cudaFuncSetAttribute(gemm_att,      cudaFuncAttributeMaxDynamicSharedMemorySize, GEMM_SMEM);
    cudaFuncSetAttribute(gemm_w1,       cudaFuncAttributeMaxDynamicSharedMemorySize, GEMM_SMEM);
    cudaFuncSetAttribute(attn2,         cudaFuncAttributeMaxDynamicSharedMemorySize, ATTN_SMEM);

    round_kernel<<<NB_ROUND, 256>>>(
        (const float4*)Wn, (const float4*)Wq, (const float4*)Wh,
        (const float4*)Wc, (const float4*)W1,
        (const float4*)nodes_glove, (const float4*)query_glove,
        (float4*)p_Wnr, (float4*)p_Wqr, (float4*)p_Whr,
        (float4*)p_Wcr, (float4*)p_W1r, (float4*)p_ngr, (float4*)p_qgr);
    nz_kernel<<<NB_NZ, 256>>>(adj, p_nzc, p_nzi, p_nzv);

    gemm_compress<<<dim3(ENC/128, 34), 256, GEMM_SMEM>>>(
        p_ngr, p_Wnr, bn, p_nc, p_L, nlen, p_qgr, p_Wqr, bq, p_qc);

    float* Lc = p_L;
    float* Ln = p_L2;
    for (int h = 0; h < HOPS; h++) {
        gemm_hm<<<dim3(ENC/128, 32), 256, GEMM_SMEM>>>(Lc, p_Whr, bh, p_hm, nlen, h);
        spmm_nz<<<MROWS, 128>>>(p_nzc, p_nzi, p_nzv, adj, p_hm, p_U, nlen, h);
        gemm_att<<<dim3(ENC/128, 32), 256, GEMM_SMEM>>>(p_U, Lc, p_Wcr, bc, nlen, Ln, h);
        float* t = Lc; Lc = Ln; Ln = t;
    }

    attn2<<<dim3(16, 8), 256, ATTN_SMEM>>>(Lc, p_qc, wa, p_nc, p_g, p_smax);
    q2n_kernel<<<dim3(BATCH, 4), 256>>>(p_smax, p_nc, p_g);

    gemm_w1<<<dim3(1, 32, 4), 256, GEMM_SMEM>>>(p_g, p_W1r, p_h1p);
    raw2_kernel<<<(MROWS*32 + 255) / 256, 256>>>(p_h1p, b1, W2, b2, p_raw);

    out_kernel<<<(BATCH*NC*32 + 255) / 256, 256>>>(mask, p_raw, out);
}

// round 17
// speedup vs baseline: 1.1433x; 1.0895x over previous
#include <cuda_runtime.h>
#include <cuda_fp16.h>
#include <cstdint>

// ---------------------------------------------------------------------------
// Problem constants
// ---------------------------------------------------------------------------
#define BATCH 8
#define NNODE 500
#define NQ    25
#define ENC   512
#define DIN   300
#define DINP  304            // weight K padded to 8-half granularity
#define NC    70
#define NET   3
#define HOPS  3
#define MROWS (BATCH*NNODE)   // 4000
#define QROWS (BATCH*NQ)      // 200
#define MAXNZ 192

// GEMM smem geometry — tile 128x128, BK=32, 4-stage.
// A: fp32 [m][k], stride 36 words (R14-identical).
// B: fp16 [n][k], stride 40 halves (conflict-free u32 frags, 16B-aligned cps).
#define NSTAGE    4
#define ASTRIDE_W 36
#define BSTRIDE_H 40
#define ABYTES (128*ASTRIDE_W*4)        // 18432
#define BBYTES (128*BSTRIDE_H*2)        // 10240
#define STAGEBYTES (ABYTES + BBYTES)    // 28672
#define GEMM_SMEM (NSTAGE*STAGEBYTES)   // 114688
#define ATTN_SMEM (NQ*ENC*4)            // 51200

// ---------------------------------------------------------------------------
// Device scratch
// ---------------------------------------------------------------------------
__device__ float g_nc  [MROWS*ENC];
__device__ float g_qc  [QROWS*ENC];
__device__ float g_L   [MROWS*ENC];
__device__ float g_L2  [MROWS*ENC];
__device__ float g_hm  [MROWS*ENC];
__device__ float g_U   [MROWS*ENC];
__device__ float g_smax[MROWS];
__device__ float g_g   [MROWS*4*ENC];
__device__ float g_h1p [4*MROWS*128];
__device__ float g_raw [MROWS];
// fp16 transposed weights [N][K] (16B-aligned for cp.async)
__device__ __align__(16) __half g_Wnh [ENC*DINP];
__device__ __align__(16) __half g_Wqh [ENC*DINP];
__device__ __align__(16) __half g_Whh [ENC*ENC];
__device__ __align__(16) __half g_Wch [ENC*2*ENC];
__device__ __align__(16) __half g_W1h [128*4*ENC];
// adjacency sparsity
__device__ int   g_nzc [MROWS];
__device__ int   g_nzi [MROWS*MAXNZ];
__device__ float g_nzv [MROWS*MAXNZ];

// ---------------------------------------------------------------------------
// Helpers
// ---------------------------------------------------------------------------
__device__ __forceinline__ float warpSum(float v) {
#pragma unroll
    for (int o = 16; o; o >>= 1) v += __shfl_xor_sync(0xffffffffu, v, o);
    return v;
}
__device__ __forceinline__ float warpMax(float v) {
#pragma unroll
    for (int o = 16; o; o >>= 1) v = fmaxf(v, __shfl_xor_sync(0xffffffffu, v, o));
    return v;
}
// pack two fp32 -> f16x2 (lo = first arg)
__device__ __forceinline__ uint32_t packh2(float lo, float hi) {
    uint32_t r;
    asm("cvt.rn.f16x2.f32 %0, %1, %2;" : "=r"(r) : "f"(hi), "f"(lo));
    return r;
}
__device__ __forceinline__ void mma_f16(float* c, const uint32_t* a, const uint32_t* b) {
    asm volatile(
        "mma.sync.aligned.m16n8k16.row.col.f32.f16.f16.f32 "
        "{%0,%1,%2,%3}, {%4,%5,%6,%7}, {%8,%9}, {%0,%1,%2,%3};"
        : "+f"(c[0]), "+f"(c[1]), "+f"(c[2]), "+f"(c[3])
        : "r"(a[0]), "r"(a[1]), "r"(a[2]), "r"(a[3]), "r"(b[0]), "r"(b[1]));
}
__device__ __forceinline__ uint32_t smem_u32(const void* p) {
    return (uint32_t)__cvta_generic_to_shared(p);
}
__device__ __forceinline__ void cp_async16(uint32_t dst, const void* src, int sz) {
    asm volatile("cp.async.ca.shared.global [%0], [%1], 16, %2;\n"
                 :: "r"(dst), "l"(src), "r"(sz));
}
__device__ __forceinline__ void cp_commit() {
    asm volatile("cp.async.commit_group;\n" ::: "memory");
}
template<int N>
__device__ __forceinline__ void cp_wait() {
    asm volatile("cp.async.wait_group %0;\n" :: "n"(N) : "memory");
}

// Zero a 128x128 fp32 output tile, guarded by r < M.
__device__ __forceinline__ void zero_tile(float* __restrict__ C, int ldc,
                                          int rowBlock, int colBlock, int M)
{
    const float4 z = make_float4(0.f, 0.f, 0.f, 0.f);
    for (int i = threadIdx.x; i < 128 * 32; i += 256) {
        int r = rowBlock + (i >> 5);
        int c4 = (i & 31) * 4;
        if (r < M)
            *reinterpret_cast<float4*>(C + (size_t)r * ldc + colBlock + c4) = z;
    }
}

// Is any row of [rowBlock, rowBlock+128) active?
__device__ __forceinline__ bool tile_active(int rowBlock, const int* __restrict__ nlen)
{
    int b0 = rowBlock / NNODE;
    int b1 = (rowBlock + 127) / NNODE;
    if (b1 >= BATCH) b1 = BATCH - 1;
    bool act = false;
    for (int b = b0; b <= b1; b++) {
        int seg = rowBlock - b * NNODE;
        if (seg < 0) seg = 0;
        if (seg < nlen[b]) act = true;
    }
    return act;
}

// ---------------------------------------------------------------------------
// convert_kernel: weights -> fp16 transposed [N][K] (zero-pad K 300->304).
// segment cums: Wnh 155648 | Wqh 311296 | Whh 573440 | Wch 1097728 | W1h 1359872
// ---------------------------------------------------------------------------
#define NB_CONV 5312   // ceil(1359872/256)
__global__ void convert_kernel(
    const float* __restrict__ Wn, const float* __restrict__ Wq,
    const float* __restrict__ Wh, const float* __restrict__ Wc,
    const float* __restrict__ W1,
    __half* __restrict__ oWn, __half* __restrict__ oWq, __half* __restrict__ oWh,
    __half* __restrict__ oWc, __half* __restrict__ oW1)
{
    int idx = blockIdx.x * 256 + threadIdx.x;
    float v; __half* dst; int off;
    if (idx < 155648) {
        off = idx; int n = off / DINP, k = off - n * DINP;
        v = (k < DIN) ? Wn[k * ENC + n] : 0.f; dst = oWn;
    } else if (idx < 311296) {
        off = idx - 155648; int n = off / DINP, k = off - n * DINP;
        v = (k < DIN) ? Wq[k * ENC + n] : 0.f; dst = oWq;
    } else if (idx < 573440) {
        off = idx - 311296; int n = off / ENC, k = off - n * ENC;
        v = Wh[k * ENC + n]; dst = oWh;
    } else if (idx < 1097728) {
        off = idx - 573440; int n = off / (2 * ENC), k = off - n * (2 * ENC);
        v = Wc[k * ENC + n]; dst = oWc;
    } else if (idx < 1359872) {
        off = idx - 1097728; int n = off / (4 * ENC), k = off - n * (4 * ENC);
        v = W1[k * 128 + n]; dst = oW1;
    } else return;
    dst[off] = __float2half(v);
}

// ---------------------------------------------------------------------------
// nz_kernel: build adjacency nz lists (one warp per row)
// ---------------------------------------------------------------------------
#define NB_NZ 500
__global__ void nz_kernel(const float* __restrict__ adj, int* __restrict__ nzc,
                          int* __restrict__ nzi, float* __restrict__ nzv)
{
    int gw = blockIdx.x * 8 + (threadIdx.x >> 5);
    int lane = threadIdx.x & 31;
    if (gw >= MROWS) return;
    int b = gw / NNODE;
    int i = gw - b * NNODE;
    const float* a0 = adj + ((size_t)b * NET) * NNODE * NNODE + (size_t)i * NNODE;
    const float* a1 = a0 + NNODE * NNODE;
    const float* a2 = a1 + NNODE * NNODE;
    int cnt = 0;
    for (int jb = 0; jb < NNODE; jb += 32) {
        int j = jb + lane;
        float v = 0.f;
        if (j < NNODE) v = a0[j] + a1[j] + a2[j];
        unsigned m = __ballot_sync(0xffffffffu, v != 0.f);
        int pos = cnt + __popc(m & ((1u << lane) - 1u));
        if (v != 0.f && pos < MAXNZ) {
            nzi[gw * MAXNZ + pos] = j;
            nzv[gw * MAXNZ + pos] = v;
        }
        cnt += __popc(m);
    }
    if (lane == 0) nzc[gw] = cnt;
}

// ---------------------------------------------------------------------------
// GEMM core: A fp32 smem [m][k] (stride 36 words), B fp16 smem [n][k]
// (stride 40 halves). A frags = float2 loads + pack; B frags = single u32.
// m16n8k16 fp16 MMA, fp32 accumulate. R11/R14 schedule.
// ---------------------------------------------------------------------------
struct GemmCtx {
    char* sh;
    int tid, lane, warp, wm, wn, tg, tq;
};

__device__ __forceinline__ void gemm_ctx_init(GemmCtx& cx, char* sh) {
    cx.sh = sh;
    cx.tid = threadIdx.x; cx.lane = cx.tid & 31; cx.warp = cx.tid >> 5;
    cx.wm = cx.warp >> 1; cx.wn = cx.warp & 1;
    cx.tg = cx.lane >> 2; cx.tq = cx.lane & 3;
}

__device__ __forceinline__ void gemm_core(
    GemmCtx& cx,
    const float* __restrict__ A, int lda,
    const float* __restrict__ Ab, int ldab, int ksplit,
    const __half* __restrict__ Wt, int ldwT,
    int rowBlock, int colBlock, int kBase, int M, int K,
    float acc[2][8][4])
{
    char* sh = cx.sh;
    const int tid = cx.tid, tg = cx.tg, tq = cx.tq, wm = cx.wm, wn = cx.wn;

    auto loadTiles = [&](int k0, int buf) {
        float*  Ad = (float*)(sh + buf * STAGEBYTES);
        __half* Bd = (__half*)(sh + buf * STAGEBYTES + ABYTES);
        // A tile 128x32 fp32: 1024 16B chunks (4 floats), 4/thread
#pragma unroll
        for (int it = 0; it < 4; it++) {
            int idx = it * 256 + tid;
            int m = idx >> 3, cc = idx & 7;
            int gr = rowBlock + m;
            int kk = k0 + cc * 4;
            int gk = kBase + kk;
            bool ok = (gr < M && kk < K);
            int gks = ok ? gk : 0;
            const float* src = (gks < ksplit)
                ? A  + (size_t)gr * lda  + gks
                : Ab + (size_t)gr * ldab + (gks - ksplit);
            cp_async16(smem_u32(Ad + m * ASTRIDE_W + cc * 4), src, ok ? 16 : 0);
        }
        // B tile 128n x 32k fp16: 512 16B chunks (8 halves), 2/thread
#pragma unroll
        for (int it = 0; it < 2; it++) {
            int idx = it * 256 + tid;
            int n = idx >> 2, cc = idx & 3;
            int kk = k0 + cc * 8;
            bool ok = (kk < K);
            int gks = ok ? (kBase + kk) : 0;
            const __half* src = Wt + (size_t)(colBlock + n) * ldwT + gks;
            cp_async16(smem_u32(Bd + n * BSTRIDE_H + cc * 8), src, ok ? 16 : 0);
        }
        cp_commit();
    };

    const int nsteps = (K + 31) / 32;

#pragma unroll
    for (int i = 0; i < NSTAGE - 1; i++)
        loadTiles(i * 32, i);

    for (int s = 0; s < nsteps; s++) {
        cp_wait<NSTAGE - 2>();
        __syncthreads();

        const int buf = s % NSTAGE;
        const float*  Asf = (const float*)(sh + buf * STAGEBYTES);
        const __half* Bsh = (const __half*)(sh + buf * STAGEBYTES + ABYTES);

#pragma unroll
        for (int ks = 0; ks < 2; ks++) {
            const int kr = ks * 16 + 2 * tq;   // k offset (elements)
            uint32_t af[2][4], bf[8][2];
#pragma unroll
            for (int mt = 0; mt < 2; mt++) {
                int r0 = wm * 32 + mt * 16 + tg;
                float2 v0 = *(const float2*)(Asf + (size_t)r0 * ASTRIDE_W + kr);
                float2 v1 = *(const float2*)(Asf + (size_t)(r0 + 8) * ASTRIDE_W + kr);
                float2 v2 = *(const float2*)(Asf + (size_t)r0 * ASTRIDE_W + kr + 8);
                float2 v3 = *(const float2*)(Asf + (size_t)(r0 + 8) * ASTRIDE_W + kr + 8);
                af[mt][0] = packh2(v0.x, v0.y);
                af[mt][1] = packh2(v1.x, v1.y);
                af[mt][2] = packh2(v2.x, v2.y);
                af[mt][3] = packh2(v3.x, v3.y);
            }
#pragma unroll
            for (int nt = 0; nt < 8; nt++) {
                int c0 = wn * 64 + nt * 8 + tg;
                bf[nt][0] = *(const uint32_t*)(Bsh + (size_t)c0 * BSTRIDE_H + kr);
                bf[nt][1] = *(const uint32_t*)(Bsh + (size_t)c0 * BSTRIDE_H + kr + 8);
            }
#pragma unroll
            for (int mt = 0; mt < 2; mt++)
#pragma unroll
                for (int nt = 0; nt < 8; nt++)
                    mma_f16(acc[mt][nt], af[mt], bf[nt]);
        }

        loadTiles((s + NSTAGE - 1) * 32, (s + NSTAGE - 1) % NSTAGE);
    }
    cp_wait<0>();
    __syncthreads();
}

// ---------------------------------------------------------------------------
// Combined compress GEMM: y<32 -> nodes (tanh -> nc, L=nc*mask), else query.
// A = raw fp32 glove inputs (ld 300); B = fp16 transposed weights (ld 304).
// ---------------------------------------------------------------------------
__global__ void __launch_bounds__(256, 1) gemm_compress(
    const float* __restrict__ ng, const __half* __restrict__ Wnh,
    const float* __restrict__ bn, float* __restrict__ nc,
    float* __restrict__ L, const int* __restrict__ nlen,
    const float* __restrict__ qg, const __half* __restrict__ Wqh,
    const float* __restrict__ bq, float* __restrict__ qc)
{
    extern __shared__ char sh_[];
    GemmCtx cx; gemm_ctx_init(cx, sh_);
    float acc[2][8][4];
#pragma unroll
    for (int i = 0; i < 2; i++)
#pragma unroll
        for (int j = 0; j < 8; j++)
#pragma unroll
            for (int l = 0; l < 4; l++) acc[i][j][l] = 0.f;

    const bool isQ = blockIdx.y >= 32;
    const float* A    = isQ ? qg : ng;
    const __half* Wt  = isQ ? Wqh : Wnh;
    const float* bias = isQ ? bq : bn;
    float* C          = isQ ? qc : nc;
    const int M       = isQ ? QROWS : MROWS;
    const int rowBlock = (isQ ? blockIdx.y - 32 : blockIdx.y) * 128;
    const int colBlock = blockIdx.x * 128;

    gemm_core(cx, A, DIN, A, DIN, DIN, Wt, DINP,
              rowBlock, colBlock, 0, M, DIN, acc);

#pragma unroll
    for (int mt = 0; mt < 2; mt++) {
#pragma unroll
        for (int half = 0; half < 2; half++) {
            int r = rowBlock + cx.wm * 32 + mt * 16 + cx.tg + half * 8;
            if (r >= M) continue;
            float rowmask = 1.f;
            if (!isQ) {
                int bb = r / NNODE;
                int ii = r - bb * NNODE;
                rowmask = (ii < nlen[bb]) ? 1.f : 0.f;
            }
#pragma unroll
            for (int nt = 0; nt < 8; nt++) {
#pragma unroll
                for (int e = 0; e < 2; e++) {
                    int c = colBlock + cx.wn * 64 + nt * 8 + cx.tq * 2 + e;
                    float v = acc[mt][nt][half * 2 + e] + bias[c];
                    size_t off = (size_t)r * ENC + c;
                    if (isQ) {
                        C[off] = v;
                    } else {
                        float t = tanhf(v);
                        C[off] = t;
                        L[off] = t * rowmask;
                    }
                }
            }
        }
    }
}

// ---------------------------------------------------------------------------
// Hop GEMM A: hm = (L @ Wh + bh) * nmask.  Dead tiles: zero only hop 0.
// ---------------------------------------------------------------------------
__global__ void __launch_bounds__(256, 1) gemm_hm(
    const float* __restrict__ Lc, const __half* __restrict__ Whh,
    const float* __restrict__ bh, float* __restrict__ hm,
    const int* __restrict__ nlen, int hop)
{
    const int rowBlock = blockIdx.y * 128;
    const int colBlock = blockIdx.x * 128;
    const int M = MROWS;

    if (!tile_active(rowBlock, nlen)) {
        if (hop == 0) zero_tile(hm, ENC, rowBlock, colBlock, M);
        return;
    }

    extern __shared__ char sh_[];
    GemmCtx cx; gemm_ctx_init(cx, sh_);
    float acc[2][8][4];
#pragma unroll
    for (int i = 0; i < 2; i++)
#pragma unroll
        for (int j = 0; j < 8; j++)
#pragma unroll
            for (int l = 0; l < 4; l++) acc[i][j][l] = 0.f;

    gemm_core(cx, Lc, ENC, Lc, ENC, ENC, Whh, ENC,
              rowBlock, colBlock, 0, M, ENC, acc);

#pragma unroll
    for (int mt = 0; mt < 2; mt++) {
#pragma unroll
        for (int half = 0; half < 2; half++) {
            int r = rowBlock + cx.wm * 32 + mt * 16 + cx.tg + half * 8;
            if (r >= M) continue;
            int bb = r / NNODE;
            int ii = r - bb * NNODE;
            float rowmask = (ii < nlen[bb]) ? 1.f : 0.f;
#pragma unroll
            for (int nt = 0; nt < 8; nt++) {
#pragma unroll
                for (int e = 0; e < 2; e++) {
                    int c = colBlock + cx.wn * 64 + nt * 8 + cx.tq * 2 + e;
                    float v = acc[mt][nt][half * 2 + e] + bh[c];
                    hm[(size_t)r * ENC + c] = v * rowmask;
                }
            }
        }
    }
}

// ---------------------------------------------------------------------------
// Hop GEMM B: att = sigmoid([U,L] @ Wc + bc)*nmask;
//             Lnew = att*tanh(U) + (1-att)*Lold   (all state fp32)
// ---------------------------------------------------------------------------
__global__ void __launch_bounds__(256, 1) gemm_att(
    const float* __restrict__ U, const float* __restrict__ Lold,
    const __half* __restrict__ Wch, const float* __restrict__ bc,
    const int* __restrict__ nlen, float* __restrict__ Lnew, int hop)
{
    const int rowBlock = blockIdx.y * 128;
    const int colBlock = blockIdx.x * 128;
    const int M = MROWS;

    if (!tile_active(rowBlock, nlen)) {
        if (hop == 0) zero_tile(Lnew, ENC, rowBlock, colBlock, M);
        return;
    }

    extern __shared__ char sh_[];
    GemmCtx cx; gemm_ctx_init(cx, sh_);
    float acc[2][8][4];
#pragma unroll
    for (int i = 0; i < 2; i++)
#pragma unroll
        for (int j = 0; j < 8; j++)
#pragma unroll
            for (int l = 0; l < 4; l++) acc[i][j][l] = 0.f;

    gemm_core(cx, U, ENC, Lold, ENC, ENC, Wch, 2 * ENC,
              rowBlock, colBlock, 0, M, 2 * ENC, acc);

#pragma unroll
    for (int mt = 0; mt < 2; mt++) {
#pragma unroll
        for (int half = 0; half < 2; half++) {
            int r = rowBlock + cx.wm * 32 + mt * 16 + cx.tg + half * 8;
            if (r >= M) continue;
            int bb = r / NNODE;
            int ii = r - bb * NNODE;
            float rowmask = (ii < nlen[bb]) ? 1.f : 0.f;
#pragma unroll
            for (int nt = 0; nt < 8; nt++) {
#pragma unroll
                for (int e = 0; e < 2; e++) {
                    int c = colBlock + cx.wn * 64 + nt * 8 + cx.tq * 2 + e;
                    float v = acc[mt][nt][half * 2 + e] + bc[c];
                    size_t off = (size_t)r * ENC + c;
                    float att = rowmask / (1.f + __expf(-v));
                    Lnew[off] = att * tanhf(U[off]) + (1.f - att) * Lold[off];
                }
            }
        }
    }
}

// ---------------------------------------------------------------------------
// W1 GEMM: split-K=4; slab z
// ---------------------------------------------------------------------------
__global__ void __launch_bounds__(256, 1) gemm_w1(
    const float* __restrict__ g, const __half* __restrict__ W1h,
    float* __restrict__ h1p)
{
    extern __shared__ char sh_[];
    GemmCtx cx; gemm_ctx_init(cx, sh_);
    float acc[2][8][4];
#pragma unroll
    for (int i = 0; i < 2; i++)
#pragma unroll
        for (int j = 0; j < 8; j++)
#pragma unroll
            for (int l = 0; l < 4; l++) acc[i][j][l] = 0.f;

    const int rowBlock = blockIdx.y * 128;
    const int colBlock = 0;
    const int z = blockIdx.z;
    const int M = MROWS;

    gemm_core(cx, g, 4*ENC, g, 4*ENC, 4*ENC, W1h, 4*ENC,
              rowBlock, colBlock, z * 512, M, 512, acc);

#pragma unroll
    for (int mt = 0; mt < 2; mt++) {
#pragma unroll
        for (int half = 0; half < 2; half++) {
            int r = rowBlock + cx.wm * 32 + mt * 16 + cx.tg + half * 8;
            if (r >= M) continue;
#pragma unroll
            for (int nt = 0; nt < 8; nt++) {
#pragma unroll
                for (int e = 0; e < 2; e++) {
                    int c = colBlock + cx.wn * 64 + nt * 8 + cx.tq * 2 + e;
                    float v = acc[mt][nt][half * 2 + e];
                    h1p[((size_t)z * M + r) * 128 + c] = v;
                }
            }
        }
    }
}

// ---------------------------------------------------------------------------
// U[m,:] = sum_t val[t]*hm[b, idx[t], :] + hm[m,:]  (fp32)
// Masked rows: zeros only at hop 0.
// ---------------------------------------------------------------------------
__global__ void spmm_nz(const int* __restrict__ nzc, const int* __restrict__ nzi,
                        const float* __restrict__ nzv, const float* __restrict__ adj,
                        const float* __restrict__ hm, float* __restrict__ U,
                        const int* __restrict__ nlen, int hop)
{
    const int m = blockIdx.x;
    const int b = m / NNODE;
    const int i = m - b * NNODE;
    const int d0 = threadIdx.x * 4;

    if (i >= nlen[b]) {
        if (hop == 0)
            *reinterpret_cast<float4*>(U + (size_t)m * ENC + d0) =
                make_float4(0.f, 0.f, 0.f, 0.f);
        return;
    }

    const float* hmb = hm + (size_t)b * NNODE * ENC;
    int cnt = nzc[m];
    float4 acc = *reinterpret_cast<const float4*>(hm + (size_t)m * ENC + d0);

    if (cnt <= MAXNZ) {
        __shared__ int   si[MAXNZ];
        __shared__ float sv[MAXNZ];
        for (int t = threadIdx.x; t < cnt; t += 128) {
            si[t] = nzi[m * MAXNZ + t];
            sv[t] = nzv[m * MAXNZ + t];
        }
        __syncthreads();
#pragma unroll 4
        for (int t = 0; t < cnt; t++) {
            float a = sv[t];
            const float4 hv = *reinterpret_cast<const float4*>(
                hmb + (size_t)si[t] * ENC + d0);
            acc.x += a * hv.x; acc.y += a * hv.y;
            acc.z += a * hv.z; acc.w += a * hv.w;
        }
    } else {
        const float* a0 = adj + ((size_t)b * NET) * NNODE * NNODE + (size_t)i * NNODE;
        const float* a1 = a0 + NNODE * NNODE;
        const float* a2 = a1 + NNODE * NNODE;
        for (int j = 0; j < NNODE; j++) {
            float a = a0[j] + a1[j] + a2[j];
            if (a != 0.f) {
                const float4 hv = *reinterpret_cast<const float4*>(
                    hmb + (size_t)j * ENC + d0);
                acc.x += a * hv.x; acc.y += a * hv.y;
                acc.z += a * hv.z; acc.w += a * hv.w;
            }
        }
    }
    *reinterpret_cast<float4*>(U + (size_t)m * ENC + d0) = acc;
}

// ---------------------------------------------------------------------------
// Attention (fused g build, segs 0-2; everything fp32)
// ---------------------------------------------------------------------------
__global__ void __launch_bounds__(256) attn2(
    const float* __restrict__ L, const float* __restrict__ qc,
    const float* __restrict__ wa, const float* __restrict__ nc,
    float* __restrict__ g, float* __restrict__ smax)
{
    extern __shared__ float qs[];   // [NQ][ENC]
    __shared__ float sqv[32];
    const int b = blockIdx.y;
    const int tile = blockIdx.x;
    const int tid = threadIdx.x, lane = tid & 31, warp = tid >> 5;

    {
        const float4* src = (const float4*)(qc + (size_t)b * NQ * ENC);
        float4* dst = (float4*)qs;
        for (int i = tid; i < NQ * ENC / 4; i += 256) dst[i] = src[i];
    }
    __syncthreads();

    for (int q = warp; q < NQ; q += 8) {
        float s = 0.f;
        for (int d = lane; d < ENC; d += 32) s += qs[q * ENC + d] * wa[ENC + d];
        s = warpSum(s);
        if (lane == 0) sqv[q] = s;
    }

    float4 wan[4], was[4];
#pragma unroll
    for (int j = 0; j < 4; j++) {
        wan[j] = *(const float4*)(wa + j * 128 + lane * 4);
        was[j] = *(const float4*)(wa + 2 * ENC + j * 128 + lane * 4);
    }
    __syncthreads();

#pragma unroll
    for (int t = 0; t < 4; t++) {
        int n = tile * 32 + t * 8 + warp;
        if (n >= NNODE) continue;
        int m = b * NNODE + n;

        float4 lw[4];
        float sn = 0.f;
#pragma unroll
        for (int j = 0; j < 4; j++) {
            float4 Lv = *(const float4*)(L + (size_t)m * ENC + j * 128 + lane * 4);
            sn += Lv.x * wan[j].x + Lv.y * wan[j].y
                + Lv.z * wan[j].z + Lv.w * wan[j].w;
            lw[j].x = Lv.x * was[j].x; lw[j].y = Lv.y * was[j].y;
            lw[j].z = Lv.z * was[j].z; lw[j].w = Lv.w * was[j].w;
        }
        sn = warpSum(sn);

        float simq = -1e30f;
#pragma unroll
        for (int q = 0; q < NQ; q++) {
            float s = 0.f;
#pragma unroll
            for (int j = 0; j < 4; j++) {
                const float4 qv = *(const float4*)(qs + q * ENC + j * 128 + lane * 4);
                s += lw[j].x * qv.x + lw[j].y * qv.y
                   + lw[j].z * qv.z + lw[j].w * qv.w;
            }
            s = warpSum(s);
            if (lane == q) simq = sn + sqv[q] + s;
        }
        float mx = warpMax(lane < NQ ? simq : -1e30f);
        float e = (lane < NQ) ? __expf(simq - mx) : 0.f;
        float Z = warpSum(e);
        float p = e / Z;
        if (lane == 0) smax[m] = mx;

        float4 accv[4];
#pragma unroll
        for (int j = 0; j < 4; j++) accv[j] = make_float4(0.f, 0.f, 0.f, 0.f);
#pragma unroll
        for (int q = 0; q < NQ; q++) {
            float pq = __shfl_sync(0xffffffffu, p, q);
#pragma unroll
            for (int j = 0; j < 4; j++) {
                const float4 qv = *(const float4*)(qs + q * ENC + j * 128 + lane * 4);
                accv[j].x += pq * qv.x; accv[j].y += pq * qv.y;
                accv[j].z += pq * qv.z; accv[j].w += pq * qv.w;
            }
        }
        float* grow = g + (size_t)m * (4 * ENC);
#pragma unroll
        for (int j = 0; j < 4; j++) {
            int d = j * 128 + lane * 4;
            float4 ncv = *(const float4*)(nc + (size_t)m * ENC + d);
            float4 g2;
            g2.x = ncv.x * accv[j].x; g2.y = ncv.y * accv[j].y;
            g2.z = ncv.z * accv[j].z; g2.w = ncv.w * accv[j].w;
            *(float4*)(grow + d)           = ncv;
            *(float4*)(grow + ENC + d)     = accv[j];
            *(float4*)(grow + 2 * ENC + d) = g2;
        }
    }
}

// ---------------------------------------------------------------------------
// q2n: grid (BATCH, 4); writes g segment 3 (fp32).
// ---------------------------------------------------------------------------
__global__ void q2n_kernel(const float* __restrict__ smax, const float* __restrict__ nc,
                           float* __restrict__ g)
{
    const int b = blockIdx.x;
    const int cy = blockIdx.y;
    const int tid = threadIdx.x;            // 256
    const int lane = tid & 31, warp = tid >> 5;
    __shared__ float w[NNODE];
    __shared__ float red[8];
    __shared__ float part[256];

    float mx = -1e30f;
    for (int n = tid; n < NNODE; n += 256) mx = fmaxf(mx, smax[b * NNODE + n]);
    mx = warpMax(mx);
    if (lane == 0) red[warp] = mx;
    __syncthreads();
    float bmax = red[0];
#pragma unroll
    for (int i = 1; i < 8; i++) bmax = fmaxf(bmax, red[i]);
    __syncthreads();

    float s = 0.f;
    for (int n = tid; n < NNODE; n += 256) {
        float e = __expf(smax[b * NNODE + n] - bmax);
        w[n] = e; s += e;
    }
    s = warpSum(s);
    if (lane == 0) red[warp] = s;
    __syncthreads();
    float Z = 0.f;
#pragma unroll
    for (int i = 0; i < 8; i++) Z += red[i];
    float inv = 1.f / Z;

    const int d = cy * 128 + (tid & 127);
    const int half = tid >> 7;
    const int n0 = half * 250, n1 = n0 + 250;

    float a = 0.f;
#pragma unroll 4
    for (int n = n0; n < n1; n++)
        a += (w[n] * inv) * nc[((size_t)b * NNODE + n) * ENC + d];
    part[tid] = a;
    __syncthreads();
    float q = part[tid & 127] + part[128 + (tid & 127)];

    for (int n = n0; n < n1; n++) {
        size_t m = (size_t)b * NNODE + n;
        g[m * (4 * ENC) + 3 * ENC + d] = nc[m * ENC + d] * q;
    }
}

// ---------------------------------------------------------------------------
// raw[m] = sum_h tanh(sum_s h1p[s][m][h] + b1[h]) * W2[h] + b2
// ---------------------------------------------------------------------------
__global__ void raw2_kernel(const float* __restrict__ h1p, const float* __restrict__ b1,
                            const float* __restrict__ W2, const float* __restrict__ b2,
                            float* __restrict__ raw)
{
    int gw = (blockIdx.x * blockDim.x + threadIdx.x) >> 5;
    int lane = threadIdx.x & 31;
    if (gw >= MROWS) return;
    const size_t stride = (size_t)MROWS * 128;
    float s = 0.f;
    for (int h = lane; h < 128; h += 32) {
        size_t o = (size_t)gw * 128 + h;
        float v = h1p[o] + h1p[o + stride] + h1p[o + 2*stride] + h1p[o + 3*stride]
                + b1[h];
        s += tanhf(v) * W2[h];
    }
    s = warpSum(s);
    if (lane == 0) raw[gw] = s + b2[0];
}

// ---------------------------------------------------------------------------
// out[b,c] = max_n f(mask*raw),  f(0) = -1e6
// ---------------------------------------------------------------------------
__global__ void out_kernel(const int* __restrict__ mask, const float* __restrict__ raw,
                           float* __restrict__ out)
{
    int gw = (blockIdx.x * blockDim.x + threadIdx.x) >> 5;
    int lane = threadIdx.x & 31;
    if (gw >= BATCH * NC) return;
    int b = gw / NC, c = gw - b * NC;
    const int* mr = mask + ((size_t)b * NC + c) * NNODE;
    const float* rr = raw + b * NNODE;
    float mx = -1e30f;
    for (int n = lane; n < NNODE; n += 32) {
        float p = (float)mr[n] * rr[n];
        if (p == 0.f) p = -1e6f;
        mx = fmaxf(mx, p);
    }
    mx = warpMax(mx);
    if (lane == 0) out[gw] = mx;
}

// ---------------------------------------------------------------------------
// Launch
// ---------------------------------------------------------------------------
extern "C" void kernel_launch(void* const* d_in, const int* in_sizes, int n_in,
                              void* d_out, int out_size)
{
    const float* nodes_glove = (const float*)d_in[0];
    const float* query_glove = (const float*)d_in[1];
    const float* adj         = (const float*)d_in[2];
    const int*   nlen        = (const int*)  d_in[3];
    const int*   mask        = (const int*)  d_in[4];
    const float* Wn = (const float*)d_in[5];
    const float* bn = (const float*)d_in[6];
    const float* Wq = (const float*)d_in[7];
    const float* bq = (const float*)d_in[8];
    const float* Wh = (const float*)d_in[9];
    const float* bh = (const float*)d_in[10];
    const float* Wc = (const float*)d_in[11];
    const float* bc = (const float*)d_in[12];
    const float* wa = (const float*)d_in[13];
    const float* W1 = (const float*)d_in[14];
    const float* b1 = (const float*)d_in[15];
    const float* W2 = (const float*)d_in[16];
    const float* b2 = (const float*)d_in[17];
    float* out = (float*)d_out;

    float *p_nc, *p_qc, *p_L, *p_L2, *p_hm, *p_U,
          *p_smax, *p_g, *p_h1p, *p_raw, *p_nzv;
    int *p_nzc, *p_nzi;
    __half *p_Wnh, *p_Wqh, *p_Whh, *p_Wch, *p_W1h;
    cudaGetSymbolAddress((void**)&p_nc,  g_nc);
    cudaGetSymbolAddress((void**)&p_qc,  g_qc);
    cudaGetSymbolAddress((void**)&p_L,   g_L);
    cudaGetSymbolAddress((void**)&p_L2,  g_L2);
    cudaGetSymbolAddress((void**)&p_hm,  g_hm);
    cudaGetSymbolAddress((void**)&p_U,   g_U);
    cudaGetSymbolAddress((void**)&p_smax,g_smax);
    cudaGetSymbolAddress((void**)&p_g,   g_g);
    cudaGetSymbolAddress((void**)&p_h1p, g_h1p);
    cudaGetSymbolAddress((void**)&p_raw, g_raw);
    cudaGetSymbolAddress((void**)&p_Wnh, g_Wnh);
    cudaGetSymbolAddress((void**)&p_Wqh, g_Wqh);
    cudaGetSymbolAddress((void**)&p_Whh, g_Whh);
    cudaGetSymbolAddress((void**)&p_Wch, g_Wch);
    cudaGetSymbolAddress((void**)&p_W1h, g_W1h);
    cudaGetSymbolAddress((void**)&p_nzc, g_nzc);
    cudaGetSymbolAddress((void**)&p_nzi, g_nzi);
    cudaGetSymbolAddress((void**)&p_nzv, g_nzv);

    cudaFuncSetAttribute(gemm_compress, cudaFuncAttributeMaxDynamicSharedMemorySize, GEMM_SMEM);
    cudaFuncSetAttribute(gemm_hm,       cudaFuncAttributeMaxDynamicSharedMemorySize, GEMM_SMEM);
    cudaFuncSetAttribute(gemm_att,      cudaFuncAttributeMaxDynamicSharedMemorySize, GEMM_SMEM);
    cudaFuncSetAttribute(gemm_w1,       cudaFuncAttributeMaxDynamicSharedMemorySize, GEMM_SMEM);
    cudaFuncSetAttribute(attn2,         cudaFuncAttributeMaxDynamicSharedMemorySize, ATTN_SMEM);

    convert_kernel<<<NB_CONV, 256>>>(Wn, Wq, Wh, Wc, W1,
                                     p_Wnh, p_Wqh, p_Whh, p_Wch, p_W1h);
    nz_kernel<<<NB_NZ, 256>>>(adj, p_nzc, p_nzi, p_nzv);

    gemm_compress<<<dim3(ENC/128, 34), 256, GEMM_SMEM>>>(
        nodes_glove, p_Wnh, bn, p_nc, p_L, nlen, query_glove, p_Wqh, bq, p_qc);

    float* Lc = p_L;
    float* Ln = p_L2;
    for (int h = 0; h < HOPS; h++) {
        gemm_hm<<<dim3(ENC/128, 32), 256, GEMM_SMEM>>>(Lc, p_Whh, bh, p_hm, nlen, h);
        spmm_nz<<<MROWS, 128>>>(p_nzc, p_nzi, p_nzv, adj, p_hm, p_U, nlen, h);
        gemm_att<<<dim3(ENC/128, 32), 256, GEMM_SMEM>>>(p_U, Lc, p_Wch, bc, nlen, Ln, h);
        float* t = Lc; Lc = Ln; Ln = t;
    }

    attn2<<<dim3(16, 8), 256, ATTN_SMEM>>>(Lc, p_qc, wa, p_nc, p_g, p_smax);
    q2n_kernel<<<dim3(BATCH, 4), 256>>>(p_smax, p_nc, p_g);

    gemm_w1<<<dim3(1, 32, 4), 256, GEMM_SMEM>>>(p_g, p_W1h, p_h1p);
    raw2_kernel<<<(MROWS*32 + 255) / 256, 256>>>(p_h1p, b1, W2, b2, p_raw);

    out_kernel<<<(BATCH*NC*32 + 255) / 256, 256>>>(mask, p_raw, out);
}